// round 15
// baseline (speedup 1.0000x reference)
#include <cuda_runtime.h>
#include <cuda_bf16.h>
#include <math.h>
#include <stdint.h>

#define N 2048
#define D 16384
#define NB 128
#define LDA 129            // padded smem stride (bank-conflict-free columns)
#define NBLK 16            // N / NB
#define PI_F 3.14159265358979323846f

// ---------------- device scratch (no allocations allowed) ----------------
__device__ float g_S[(size_t)N * N];        // gram / sigma / L (lower, in place)
__device__ float g_W[(size_t)N * N];        // L^{-1} (lower)
__device__ float g_invD[NBLK * NB * NB];    // per-panel inv(L11)
__device__ float g_T2[(size_t)1024 * 1024]; // D&C inversion scratch
__device__ float g_diag[N];                 // diag snapshot
__device__ float g_scal[4];                 // [0]=trace acc, [1]=proj acc
__device__ __nv_bfloat16 g_hi[(size_t)N * D];
__device__ __nv_bfloat16 g_lo[(size_t)N * D];
__device__ __nv_bfloat16 g_Phi[(size_t)N * NB];  // TRSM panel, bf16 hi
__device__ __nv_bfloat16 g_Plo[(size_t)N * NB];  // TRSM panel, bf16 lo

// ==========================================================================
__device__ __forceinline__ uint32_t smem_u32(const void* p) {
    uint32_t a;
    asm("{ .reg .u64 t; cvta.to.shared.u64 t, %1; cvt.u32.u64 %0, t; }"
        : "=r"(a) : "l"(p));
    return a;
}
__device__ __forceinline__ uint32_t bf2pack(float a, float b) {
    __nv_bfloat162 h(__float2bfloat16(a), __float2bfloat16(b));
    return *(uint32_t*)&h;
}

// ==========================================================================
// split conversion: x -> hi (bf16) only (gram is pure hi*hi)
// ==========================================================================
__global__ void split_kernel(const float* __restrict__ x)
{
    size_t total = (size_t)N * D / 4;
    const float4* x4 = (const float4*)x;
    for (size_t i = blockIdx.x * (size_t)blockDim.x + threadIdx.x; i < total;
         i += (size_t)gridDim.x * blockDim.x) {
        float4 v = x4[i];
        __nv_bfloat162* hp = (__nv_bfloat162*)(g_hi + i * 4);
        hp[0] = __nv_bfloat162(__float2bfloat16(v.x), __float2bfloat16(v.y));
        hp[1] = __nv_bfloat162(__float2bfloat16(v.z), __float2bfloat16(v.w));
    }
}

// ==========================================================================
// templated bf16-split NT mma kernel over lower tile pairs:
// NPROD=1: acc = Ahi*Bhi^T (gram)  NPROD=3: + Ahi*Blo^T + Alo*Bhi^T (SYRK)
// MODE=0:  C = clip(acc*scale, -1, 1) + writes g_diag on diag tiles
// MODE=1:  C -= acc
// ==========================================================================
#define BKG 32
#define GTILE_B (128 * 40 * 2)
#define GRAM_SMEM (2 * 4 * GTILE_B)

__device__ __forceinline__ void ldsm_x4(uint32_t* r, uint32_t addr) {
    asm volatile("ldmatrix.sync.aligned.m8n8.x4.shared.b16 {%0,%1,%2,%3}, [%4];"
                 : "=r"(r[0]), "=r"(r[1]), "=r"(r[2]), "=r"(r[3]) : "r"(addr));
}
__device__ __forceinline__ void ldsm_x2(uint32_t* r, uint32_t addr) {
    asm volatile("ldmatrix.sync.aligned.m8n8.x2.shared.b16 {%0,%1}, [%2];"
                 : "=r"(r[0]), "=r"(r[1]) : "r"(addr));
}
__device__ __forceinline__ void ldsm_x2_trans(uint32_t* r, uint32_t addr) {
    asm volatile("ldmatrix.sync.aligned.m8n8.x2.trans.shared.b16 {%0,%1}, [%2];"
                 : "=r"(r[0]), "=r"(r[1]) : "r"(addr));
}
__device__ __forceinline__ void mma_bf16(float* d, const uint32_t* a,
                                         const uint32_t* b) {
    asm volatile(
        "mma.sync.aligned.m16n8k16.row.col.f32.bf16.bf16.f32 "
        "{%0,%1,%2,%3}, {%4,%5,%6,%7}, {%8,%9}, {%0,%1,%2,%3};"
        : "+f"(d[0]), "+f"(d[1]), "+f"(d[2]), "+f"(d[3])
        : "r"(a[0]), "r"(a[1]), "r"(a[2]), "r"(a[3]), "r"(b[0]), "r"(b[1]));
}
#define CP_ASYNC(dst, src) \
    asm volatile("cp.async.cg.shared.global [%0], [%1], 16;" \
                 :: "r"(dst), "l"(src))
#define CP_COMMIT() asm volatile("cp.async.commit_group;" ::: "memory")

template <int NPROD, int MODE>
__global__ __launch_bounds__(256, 1)
void mma_nt_kernel(const __nv_bfloat16* __restrict__ Ahi,
                   const __nv_bfloat16* __restrict__ Alo,
                   const __nv_bfloat16* __restrict__ Bhi,
                   const __nv_bfloat16* __restrict__ Blo,
                   size_t lda, float* __restrict__ Cbase, int ldc,
                   int K, float scale)
{
    extern __shared__ char dsm[];
    uint32_t sbase = smem_u32(dsm);

    int tid  = threadIdx.x;
    int wid  = tid >> 5;
    int lane = tid & 31;

    int t = blockIdx.x;
    int bi = (int)((sqrtf(8.f * (float)t + 1.f) - 1.f) * 0.5f);
    while ((bi + 1) * (bi + 2) / 2 <= t) bi++;
    while (bi * (bi + 1) / 2 > t) bi--;
    int bj = t - bi * (bi + 1) / 2;

    const __nv_bfloat16* srcs[4] = {
        Ahi + (size_t)bi * 128 * lda,
        Alo + (size_t)bi * 128 * lda,
        Bhi + (size_t)bj * 128 * lda,
        Blo + (size_t)bj * 128 * lda
    };

    int m0w = (wid & 1) * 64;
    int n0w = (wid >> 1) * 32;

    float acc[4][4][4];
#pragma unroll
    for (int im = 0; im < 4; im++)
#pragma unroll
        for (int jn = 0; jn < 4; jn++)
#pragma unroll
            for (int e = 0; e < 4; e++) acc[im][jn][e] = 0.f;

    const int S = K / BKG;

    {
#pragma unroll
        for (int it = 0; it < 8; it++) {
            int idx = tid + it * 256;
            int tile = idx >> 9;
            int rem = idx & 511;
            int r = rem >> 2, ch = rem & 3;
            if (NPROD == 1 && (tile & 1)) continue;
            if (NPROD == 2 && tile == 1) continue;
            uint32_t dst = sbase + (uint32_t)tile * GTILE_B + r * 80 + ch * 16;
            CP_ASYNC(dst, srcs[tile] + (size_t)r * lda + ch * 8);
        }
        CP_COMMIT();
    }

#pragma unroll 1
    for (int s = 0; s < S; s++) {
        if (s + 1 < S) {
            int k0 = (s + 1) * BKG;
            uint32_t boff = (uint32_t)((s + 1) & 1) * (4 * GTILE_B);
#pragma unroll
            for (int it = 0; it < 8; it++) {
                int idx = tid + it * 256;
                int tile = idx >> 9;
                int rem = idx & 511;
                int r = rem >> 2, ch = rem & 3;
                if (NPROD == 1 && (tile & 1)) continue;
                if (NPROD == 2 && tile == 1) continue;
                uint32_t dst = sbase + boff + (uint32_t)tile * GTILE_B +
                               r * 80 + ch * 16;
                CP_ASYNC(dst, srcs[tile] + (size_t)r * lda + k0 + ch * 8);
            }
            CP_COMMIT();
            asm volatile("cp.async.wait_group 1;" ::: "memory");
        } else {
            asm volatile("cp.async.wait_group 0;" ::: "memory");
        }
        __syncthreads();

        uint32_t buf = sbase + (uint32_t)(s & 1) * (4 * GTILE_B);
        uint32_t Ahi_b = buf;
        uint32_t Alo_b = buf + GTILE_B;
        uint32_t Bhi_b = buf + 2 * GTILE_B;
        uint32_t Blo_b = buf + 3 * GTILE_B;

#pragma unroll
        for (int ks = 0; ks < 2; ks++) {
            int kof = ks * 16;
            int arow = lane & 15;
            int acol = kof + 8 * (lane >> 4);
            uint32_t ah[4][4], al[4][4];
#pragma unroll
            for (int im = 0; im < 4; im++) {
                uint32_t ro = (uint32_t)(m0w + im * 16 + arow) * 80 + acol * 2;
                ldsm_x4(ah[im], Ahi_b + ro);
                if (NPROD == 3) ldsm_x4(al[im], Alo_b + ro);
            }
            int brow = lane & 7;
            int bcol = kof + 8 * ((lane >> 3) & 1);
            uint32_t bh[4][2], bl[4][2];
#pragma unroll
            for (int jn = 0; jn < 4; jn++) {
                uint32_t ro = (uint32_t)(n0w + jn * 8 + brow) * 80 + bcol * 2;
                ldsm_x2(bh[jn], Bhi_b + ro);
                if (NPROD >= 2) ldsm_x2(bl[jn], Blo_b + ro);
            }
#pragma unroll
            for (int im = 0; im < 4; im++)
#pragma unroll
                for (int jn = 0; jn < 4; jn++) {
                    mma_bf16(acc[im][jn], ah[im], bh[jn]);
                    if (NPROD >= 2) mma_bf16(acc[im][jn], ah[im], bl[jn]);
                    if (NPROD == 3) mma_bf16(acc[im][jn], al[im], bh[jn]);
                }
        }
        __syncthreads();
    }

#pragma unroll
    for (int im = 0; im < 4; im++) {
        int row = bi * 128 + m0w + im * 16 + (lane >> 2);
#pragma unroll
        for (int jn = 0; jn < 4; jn++) {
            int col = bj * 128 + n0w + jn * 8 + (lane & 3) * 2;
            float* p0 = Cbase + (size_t)row * ldc + col;
            float* p1 = Cbase + (size_t)(row + 8) * ldc + col;
            if (MODE == 0) {
                float v0 = fminf(fmaxf(acc[im][jn][0] * scale, -1.f), 1.f);
                float v1 = fminf(fmaxf(acc[im][jn][1] * scale, -1.f), 1.f);
                float v2 = fminf(fmaxf(acc[im][jn][2] * scale, -1.f), 1.f);
                float v3 = fminf(fmaxf(acc[im][jn][3] * scale, -1.f), 1.f);
                p0[0] = v0; p0[1] = v1; p1[0] = v2; p1[1] = v3;
                if (bi == bj) {   // fused diag snapshot
                    if (col == row)         g_diag[row]     = v0;
                    if (col + 1 == row)     g_diag[row]     = v1;
                    if (col == row + 8)     g_diag[row + 8] = v2;
                    if (col + 1 == row + 8) g_diag[row + 8] = v3;
                }
            } else {
                p0[0] -= acc[im][jn][0];
                p0[1] -= acc[im][jn][1];
                p1[0] -= acc[im][jn][2];
                p1[1] -= acc[im][jn][3];
            }
        }
    }
}

// ==========================================================================
// TRSM panel via mma with on-the-fly fp32->bf16 hi/lo split (3 products):
// C[rows x 128] = A[rows x 128] * B[128 x 128]^T (B = invD), in place into S,
// plus bf16 hi/lo panels for the trailing SYRK. One CTA per 128-row slab.
// ==========================================================================
#define TS_A 10240                   // 128 rows * 80 B (32 bf16 + pad)
#define TS_STAGE (4 * TS_A)          // Ahi, Alo, Bhi, Blo
#define TS_SMEM (2 * TS_STAGE)       // 81920 B

__global__ __launch_bounds__(256, 1)
void gemm_nt_split_mma(const float* __restrict__ A, int lda,
                       const float* __restrict__ B,      // 128x128, ldb=128
                       float* __restrict__ Cs, int ldcs,
                       __nv_bfloat16* __restrict__ Phi,
                       __nv_bfloat16* __restrict__ Plo)
{
    extern __shared__ char dsm[];
    uint32_t sbase = smem_u32(dsm);

    int tid = threadIdx.x, wid = tid >> 5, lane = tid & 31;
    int bi = blockIdx.x;
    int m0w = (wid & 1) * 64;
    int n0w = (wid >> 1) * 32;

    const float* Abase = A + (size_t)bi * 128 * lda;

    float acc[4][4][4];
#pragma unroll
    for (int im = 0; im < 4; im++)
#pragma unroll
        for (int jn = 0; jn < 4; jn++)
#pragma unroll
            for (int e = 0; e < 4; e++) acc[im][jn][e] = 0.f;

    const int S = 4;   // K = 128, BK = 32

    float4 ra[4], rb[4];
    auto ldreg = [&](int s) {
#pragma unroll
        for (int it = 0; it < 4; it++) {
            int idx = tid + it * 256;
            int r = idx >> 3, f = idx & 7;
            ra[it] = *(const float4*)(Abase + (size_t)r * lda + s * 32 + f * 4);
            rb[it] = *(const float4*)(B + (size_t)r * 128 + s * 32 + f * 4);
        }
    };
    auto streg = [&](int b) {
        char* sm = dsm + (size_t)b * TS_STAGE;
#pragma unroll
        for (int it = 0; it < 4; it++) {
            int idx = tid + it * 256;
            int r = idx >> 3, f = idx & 7;
            float4 v = ra[it];
            float hx = __bfloat162float(__float2bfloat16(v.x));
            float hy = __bfloat162float(__float2bfloat16(v.y));
            float hz = __bfloat162float(__float2bfloat16(v.z));
            float hw = __bfloat162float(__float2bfloat16(v.w));
            uint2 hi = { bf2pack(v.x, v.y), bf2pack(v.z, v.w) };
            uint2 lo = { bf2pack(v.x - hx, v.y - hy),
                         bf2pack(v.z - hz, v.w - hw) };
            *(uint2*)(sm + r * 80 + f * 8)        = hi;
            *(uint2*)(sm + TS_A + r * 80 + f * 8) = lo;
            float4 w = rb[it];
            float gx = __bfloat162float(__float2bfloat16(w.x));
            float gy = __bfloat162float(__float2bfloat16(w.y));
            float gz = __bfloat162float(__float2bfloat16(w.z));
            float gw = __bfloat162float(__float2bfloat16(w.w));
            uint2 bh = { bf2pack(w.x, w.y), bf2pack(w.z, w.w) };
            uint2 bl = { bf2pack(w.x - gx, w.y - gy),
                         bf2pack(w.z - gz, w.w - gw) };
            *(uint2*)(sm + 2 * TS_A + r * 80 + f * 8) = bh;
            *(uint2*)(sm + 3 * TS_A + r * 80 + f * 8) = bl;
        }
    };

    ldreg(0);
    streg(0);
    __syncthreads();

#pragma unroll 1
    for (int s = 0; s < S; s++) {
        if (s + 1 < S) ldreg(s + 1);

        uint32_t buf = sbase + (uint32_t)(s & 1) * TS_STAGE;
        uint32_t Ahi_b = buf;
        uint32_t Alo_b = buf + TS_A;
        uint32_t Bhi_b = buf + 2 * TS_A;
        uint32_t Blo_b = buf + 3 * TS_A;

#pragma unroll
        for (int ks = 0; ks < 2; ks++) {
            int kof = ks * 16;
            int arow = lane & 15;
            int acol = kof + 8 * (lane >> 4);
            uint32_t ah[4][4], al[4][4];
#pragma unroll
            for (int im = 0; im < 4; im++) {
                uint32_t ro = (uint32_t)(m0w + im * 16 + arow) * 80 + acol * 2;
                ldsm_x4(ah[im], Ahi_b + ro);
                ldsm_x4(al[im], Alo_b + ro);
            }
            int brow = lane & 7;
            int bcol = kof + 8 * ((lane >> 3) & 1);
            uint32_t bh[4][2], bl[4][2];
#pragma unroll
            for (int jn = 0; jn < 4; jn++) {
                uint32_t ro = (uint32_t)(n0w + jn * 8 + brow) * 80 + bcol * 2;
                ldsm_x2(bh[jn], Bhi_b + ro);
                ldsm_x2(bl[jn], Blo_b + ro);
            }
#pragma unroll
            for (int im = 0; im < 4; im++)
#pragma unroll
                for (int jn = 0; jn < 4; jn++) {
                    mma_bf16(acc[im][jn], ah[im], bh[jn]);
                    mma_bf16(acc[im][jn], ah[im], bl[jn]);
                    mma_bf16(acc[im][jn], al[im], bh[jn]);
                }
        }

        if (s + 1 < S) streg((s + 1) & 1);
        __syncthreads();
    }

#pragma unroll
    for (int im = 0; im < 4; im++) {
        int row = bi * 128 + m0w + im * 16 + (lane >> 2);
#pragma unroll
        for (int jn = 0; jn < 4; jn++) {
            int col = n0w + jn * 8 + (lane & 3) * 2;
#pragma unroll
            for (int e = 0; e < 4; e++) {
                int rr = row + (e >> 1) * 8;
                int cc = col + (e & 1);
                float v = acc[im][jn][e];
                Cs[(size_t)rr * ldcs + cc] = v;
                __nv_bfloat16 h = __float2bfloat16(v);
                Phi[(size_t)rr * NB + cc] = h;
                Plo[(size_t)rr * NB + cc] =
                    __float2bfloat16(v - __bfloat162float(h));
            }
        }
    }
}

// ==========================================================================
// batched NN mma GEMM with on-the-fly fp32 -> bf16 hi/lo split (3 products)
// MASKA/MASKB: diag-aligned lower-triangular operand masking.
// ==========================================================================
#define NNT_A 10240                  // 128 rows * 80 B
#define NNT_B 8704                   // 32 rows * 272 B
#define NN_STAGE (2 * NNT_A + 2 * NNT_B)
#define NN_SMEM (2 * NN_STAGE)       // 75776 B

template <int MASKA, int MASKB>
__global__ __launch_bounds__(256, 1)
void gemm_nn_mma(const float* __restrict__ A, size_t strA, int lda,
                 const float* __restrict__ B, size_t strB, int ldb,
                 float* __restrict__ C, size_t strC, int ldc,
                 int K, float alpha)
{
    A += (size_t)blockIdx.z * strA;
    B += (size_t)blockIdx.z * strB;
    C += (size_t)blockIdx.z * strC;

    extern __shared__ char dsm[];
    uint32_t sbase = smem_u32(dsm);

    int tid = threadIdx.x, wid = tid >> 5, lane = tid & 31;
    int bi = blockIdx.y, bj = blockIdx.x;
    int m0w = (wid & 1) * 64;
    int n0w = (wid >> 1) * 32;

    float acc[4][4][4];
#pragma unroll
    for (int im = 0; im < 4; im++)
#pragma unroll
        for (int jn = 0; jn < 4; jn++)
#pragma unroll
            for (int e = 0; e < 4; e++) acc[im][jn][e] = 0.f;

    const int S = K / 32;

    float4 ra[4], rb[4];

    auto ldreg = [&](int s) {
#pragma unroll
        for (int it = 0; it < 4; it++) {
            int idx = tid + it * 256;
            int r = idx >> 3, f = idx & 7;
            float4 v = *(const float4*)(A + (size_t)(bi * 128 + r) * lda +
                                        s * 32 + f * 4);
            if (MASKA) {
                int row = bi * 128 + r;
                int cb = s * 32 + f * 4;
                if (cb + 0 > row) v.x = 0.f;
                if (cb + 1 > row) v.y = 0.f;
                if (cb + 2 > row) v.z = 0.f;
                if (cb + 3 > row) v.w = 0.f;
            }
            ra[it] = v;
        }
#pragma unroll
        for (int it = 0; it < 4; it++) {
            int idx = tid + it * 256;
            int kk = idx >> 5, f = idx & 31;
            float4 v = *(const float4*)(B + (size_t)(s * 32 + kk) * ldb +
                                        bj * 128 + f * 4);
            if (MASKB) {
                int krow = s * 32 + kk;
                int cb = bj * 128 + f * 4;
                if (cb + 0 > krow) v.x = 0.f;
                if (cb + 1 > krow) v.y = 0.f;
                if (cb + 2 > krow) v.z = 0.f;
                if (cb + 3 > krow) v.w = 0.f;
            }
            rb[it] = v;
        }
    };

    auto streg = [&](int b) {
        char* sm = dsm + (size_t)b * NN_STAGE;
#pragma unroll
        for (int it = 0; it < 4; it++) {
            int idx = tid + it * 256;
            int r = idx >> 3, f = idx & 7;
            float4 v = ra[it];
            float hx = __bfloat162float(__float2bfloat16(v.x));
            float hy = __bfloat162float(__float2bfloat16(v.y));
            float hz = __bfloat162float(__float2bfloat16(v.z));
            float hw = __bfloat162float(__float2bfloat16(v.w));
            uint2 hi = { bf2pack(v.x, v.y), bf2pack(v.z, v.w) };
            uint2 lo = { bf2pack(v.x - hx, v.y - hy),
                         bf2pack(v.z - hz, v.w - hw) };
            *(uint2*)(sm + r * 80 + f * 8)         = hi;
            *(uint2*)(sm + NNT_A + r * 80 + f * 8) = lo;
        }
#pragma unroll
        for (int it = 0; it < 4; it++) {
            int idx = tid + it * 256;
            int kk = idx >> 5, f = idx & 31;
            float4 v = rb[it];
            float hx = __bfloat162float(__float2bfloat16(v.x));
            float hy = __bfloat162float(__float2bfloat16(v.y));
            float hz = __bfloat162float(__float2bfloat16(v.z));
            float hw = __bfloat162float(__float2bfloat16(v.w));
            uint2 hi = { bf2pack(v.x, v.y), bf2pack(v.z, v.w) };
            uint2 lo = { bf2pack(v.x - hx, v.y - hy),
                         bf2pack(v.z - hz, v.w - hw) };
            *(uint2*)(sm + 2 * NNT_A + kk * 272 + f * 8)         = hi;
            *(uint2*)(sm + 2 * NNT_A + NNT_B + kk * 272 + f * 8) = lo;
        }
    };

    ldreg(0);
    streg(0);
    __syncthreads();

#pragma unroll 1
    for (int s = 0; s < S; s++) {
        if (s + 1 < S) ldreg(s + 1);

        uint32_t buf = sbase + (uint32_t)(s & 1) * NN_STAGE;
        uint32_t Ahi_b = buf;
        uint32_t Alo_b = buf + NNT_A;
        uint32_t Bhi_b = buf + 2 * NNT_A;
        uint32_t Blo_b = buf + 2 * NNT_A + NNT_B;

#pragma unroll
        for (int ks = 0; ks < 2; ks++) {
            int kof = ks * 16;
            int arow = lane & 15;
            int acol = kof + 8 * (lane >> 4);
            uint32_t ah[4][4], al[4][4];
#pragma unroll
            for (int im = 0; im < 4; im++) {
                uint32_t ro = (uint32_t)(m0w + im * 16 + arow) * 80 + acol * 2;
                ldsm_x4(ah[im], Ahi_b + ro);
                ldsm_x4(al[im], Alo_b + ro);
            }
            int l16 = lane & 15;
            int brow = kof + (l16 & 7) + 8 * (l16 >> 3);
            uint32_t bh[4][2], bl[4][2];
#pragma unroll
            for (int jn = 0; jn < 4; jn++) {
                int n0 = n0w + jn * 8;
                uint32_t ro = (uint32_t)brow * 272 + n0 * 2;
                ldsm_x2_trans(bh[jn], Bhi_b + ro);
                ldsm_x2_trans(bl[jn], Blo_b + ro);
            }
#pragma unroll
            for (int im = 0; im < 4; im++)
#pragma unroll
                for (int jn = 0; jn < 4; jn++) {
                    mma_bf16(acc[im][jn], ah[im], bh[jn]);
                    mma_bf16(acc[im][jn], ah[im], bl[jn]);
                    mma_bf16(acc[im][jn], al[im], bh[jn]);
                }
        }

        if (s + 1 < S) streg((s + 1) & 1);
        __syncthreads();
    }

#pragma unroll
    for (int im = 0; im < 4; im++) {
        int row = bi * 128 + m0w + im * 16 + (lane >> 2);
#pragma unroll
        for (int jn = 0; jn < 4; jn++) {
            int col = bj * 128 + n0w + jn * 8 + (lane & 3) * 2;
            C[(size_t)row * ldc + col]           = alpha * acc[im][jn][0];
            C[(size_t)row * ldc + col + 1]       = alpha * acc[im][jn][1];
            C[(size_t)(row + 8) * ldc + col]     = alpha * acc[im][jn][2];
            C[(size_t)(row + 8) * ldc + col + 1] = alpha * acc[im][jn][3];
        }
    }
}

// ==========================================================================
__global__ void step_kernel(const float* __restrict__ alpha_p)
{
    int j = blockIdx.x * 32 + threadIdx.x;
    int i = blockIdx.y * 8 + threadIdx.y;
    if (i >= N || j > i) return;
    float a  = *alpha_p;
    float a2 = a * a;
    float cross = sqrtf(g_diag[i] * g_diag[j]);
    float s = g_S[(size_t)i * N + j];
    float m = fminf(fmaxf(s / cross, -1.f), 1.f);
    float q = 1.f - m * m;
    float sq, ac;
    if (q > 0.f) { sq = sqrtf(q); ac = acosf(m); }
    else         { sq = 0.f;      ac = (m > 0.f) ? 0.f : PI_F; }
    float f  = (sq + m * (PI_F - ac)) / PI_F;
    float ts = cross * f;
    float ov = (s + a2 * ts) / (1.f + a2);
    g_S[(size_t)i * N + j] = fminf(fmaxf(ov, -1.f), 1.f);
}

// ==========================================================================
// panel factorization + inversion of 128x128 diag block (512 threads).
// Epilogue writes L to S, inv(L11) to g_invD AND to W's diag block.
// ==========================================================================
#define PT 512
__global__ __launch_bounds__(PT, 1)
void potrf_invert(int kb)
{
    extern __shared__ float sh[];
    float* A = sh;                 // NB x NB stride LDA (L, lower)
    float* W = sh + NB * LDA;      // NB x NB stride LDA (inv(L), lower)
    __shared__ float Ts[3 * 1056];
    int tid = threadIdx.x;
    int base = kb * NB;

    for (int idx = tid; idx < NB * 32; idx += PT) {
        int i = idx >> 5, j4 = (idx & 31) << 2;
        float4 v = *(const float4*)&g_S[(size_t)(base + i) * N + base + j4];
        A[i * LDA + j4 + 0] = v.x;
        A[i * LDA + j4 + 1] = v.y;
        A[i * LDA + j4 + 2] = v.z;
        A[i * LDA + j4 + 3] = v.w;
    }
    __syncthreads();

    for (int p = 0; p < 4; p++) {
        int off = p * 32;

        if (tid < 32) {
            const unsigned FULL = 0xffffffffu;
            int r = tid;
            float ar[32];
#pragma unroll
            for (int t = 0; t < 32; t++)
                ar[t] = (t <= r) ? A[(off + r) * LDA + off + t] : 0.f;
            float rs_reg = 0.f;
#pragma unroll
            for (int j = 0; j < 32; j++) {
                float d   = __shfl_sync(FULL, ar[j], j);
                float rsj = rsqrtf(d);
                float lj  = ar[j] * rsj;
                ar[j] = lj;
                if (r == j) rs_reg = rsj;
#pragma unroll
                for (int t = j + 1; t < 32; t++) {
                    float ltj = __shfl_sync(FULL, lj, t);
                    ar[t] -= lj * ltj;
                }
            }
            int c = r;
            float w[32];
#pragma unroll
            for (int t = 0; t < 32; t++) w[t] = 0.f;
#pragma unroll
            for (int i = 0; i < 32; i++) {
                float s = (i == c) ? 1.f : 0.f;
#pragma unroll
                for (int t = 0; t < i; t++) {
                    float lit = __shfl_sync(FULL, ar[t], i);
                    s -= lit * w[t];
                }
                float rsi = __shfl_sync(FULL, rs_reg, i);
                w[i] = (i >= c) ? s * rsi : 0.f;
            }
#pragma unroll
            for (int t = 0; t < 32; t++)
                if (t <= r) A[(off + r) * LDA + off + t] = ar[t];
#pragma unroll
            for (int i = 0; i < 32; i++)
                W[(off + i) * LDA + off + c] = w[i];
        }
        __syncthreads();

        int nr = NB - off - 32;
        if (nr > 0) {
            int ntr = (nr >> 2) * 8;
            float acc[4][4];
            int tr = 0, tc = 0;
            if (tid < ntr) {
                tr = (tid >> 3) * 4;
                tc = (tid & 7) * 4;
#pragma unroll
                for (int r = 0; r < 4; r++)
#pragma unroll
                    for (int cidx = 0; cidx < 4; cidx++) acc[r][cidx] = 0.f;
#pragma unroll 8
                for (int k = 0; k < 32; k++) {
                    float av[4], wv[4];
#pragma unroll
                    for (int r = 0; r < 4; r++)
                        av[r] = A[(off + 32 + tr + r) * LDA + off + k];
#pragma unroll
                    for (int cidx = 0; cidx < 4; cidx++)
                        wv[cidx] = W[(off + tc + cidx) * LDA + off + k];
#pragma unroll
                    for (int r = 0; r < 4; r++)
#pragma unroll
                        for (int cidx = 0; cidx < 4; cidx++)
                            acc[r][cidx] += av[r] * wv[cidx];
                }
            }
            __syncthreads();
            if (tid < ntr) {
#pragma unroll
                for (int r = 0; r < 4; r++)
#pragma unroll
                    for (int cidx = 0; cidx < 4; cidx++)
                        A[(off + 32 + tr + r) * LDA + off + tc + cidx] =
                            acc[r][cidx];
            }
            __syncthreads();

            int nt = nr >> 2;
            int ntot = nt * (nt + 1) / 2;
            for (int tId = tid; tId < ntot; tId += PT) {
                int ti = (int)((sqrtf(8.f * (float)tId + 1.f) - 1.f) * 0.5f);
                while ((ti + 1) * (ti + 2) / 2 <= tId) ti++;
                while (ti * (ti + 1) / 2 > tId) ti--;
                int tj = tId - ti * (ti + 1) / 2;
                int i0 = off + 32 + ti * 4;
                int t0 = off + 32 + tj * 4;
                float a2[4][4];
#pragma unroll
                for (int r = 0; r < 4; r++)
#pragma unroll
                    for (int cidx = 0; cidx < 4; cidx++) a2[r][cidx] = 0.f;
#pragma unroll 8
                for (int k = 0; k < 32; k++) {
                    float av[4], bv[4];
#pragma unroll
                    for (int r = 0; r < 4; r++)
                        av[r] = A[(i0 + r) * LDA + off + k];
#pragma unroll
                    for (int cidx = 0; cidx < 4; cidx++)
                        bv[cidx] = A[(t0 + cidx) * LDA + off + k];
#pragma unroll
                    for (int r = 0; r < 4; r++)
#pragma unroll
                        for (int cidx = 0; cidx < 4; cidx++)
                            a2[r][cidx] += av[r] * bv[cidx];
                }
#pragma unroll
                for (int r = 0; r < 4; r++)
#pragma unroll
                    for (int cidx = 0; cidx < 4; cidx++) {
                        int ii = i0 + r, tt = t0 + cidx;
                        if (tt <= ii) A[ii * LDA + tt] -= a2[r][cidx];
                    }
            }
            __syncthreads();
        }
    }

    for (int ib = 1; ib < 4; ib++) {
        for (int tId = tid; tId < ib * 64; tId += PT) {
            int j = tId >> 6;
            int e = tId & 63;
            int r0 = (e >> 3) * 4, c0 = (e & 7) * 4;
            float acc[4][4];
#pragma unroll
            for (int r = 0; r < 4; r++)
#pragma unroll
                for (int cidx = 0; cidx < 4; cidx++) acc[r][cidx] = 0.f;
            for (int tb = j; tb < ib; tb++) {
#pragma unroll 8
                for (int k = 0; k < 32; k++) {
                    float lv[4], wv[4];
#pragma unroll
                    for (int r = 0; r < 4; r++)
                        lv[r] = A[(32 * ib + r0 + r) * LDA + 32 * tb + k];
#pragma unroll
                    for (int cidx = 0; cidx < 4; cidx++)
                        wv[cidx] = W[(32 * tb + k) * LDA + 32 * j + c0 + cidx];
#pragma unroll
                    for (int r = 0; r < 4; r++)
#pragma unroll
                        for (int cidx = 0; cidx < 4; cidx++)
                            acc[r][cidx] += lv[r] * wv[cidx];
                }
            }
#pragma unroll
            for (int r = 0; r < 4; r++)
#pragma unroll
                for (int cidx = 0; cidx < 4; cidx++)
                    Ts[j * 1056 + (r0 + r) * 33 + c0 + cidx] = acc[r][cidx];
        }
        __syncthreads();
        for (int tId = tid; tId < ib * 64; tId += PT) {
            int j = tId >> 6;
            int e = tId & 63;
            int r0 = (e >> 3) * 4, c0 = (e & 7) * 4;
            float acc[4][4];
#pragma unroll
            for (int r = 0; r < 4; r++)
#pragma unroll
                for (int cidx = 0; cidx < 4; cidx++) acc[r][cidx] = 0.f;
#pragma unroll 8
            for (int k = 0; k < 32; k++) {
                float wv[4], tv[4];
#pragma unroll
                for (int r = 0; r < 4; r++)
                    wv[r] = W[(32 * ib + r0 + r) * LDA + 32 * ib + k];
#pragma unroll
                for (int cidx = 0; cidx < 4; cidx++)
                    tv[cidx] = Ts[j * 1056 + k * 33 + c0 + cidx];
#pragma unroll
                for (int r = 0; r < 4; r++)
#pragma unroll
                    for (int cidx = 0; cidx < 4; cidx++)
                        acc[r][cidx] += wv[r] * tv[cidx];
            }
#pragma unroll
            for (int r = 0; r < 4; r++)
#pragma unroll
                for (int cidx = 0; cidx < 4; cidx++)
                    W[(32 * ib + r0 + r) * LDA + 32 * j + c0 + cidx] =
                        -acc[r][cidx];
        }
        __syncthreads();
    }

    for (int idx = tid; idx < NB * NB; idx += PT) {
        int i = idx >> 7, j = idx & 127;
        if (j <= i) g_S[(size_t)(base + i) * N + base + j] = A[i * LDA + j];
        float wv = ((j >> 5) <= (i >> 5)) ? W[i * LDA + j] : 0.f;
        g_invD[(size_t)kb * NB * NB + idx] = wv;
        g_W[(size_t)(base + i) * N + base + j] = wv;   // fused copy_diag
    }
}

// ==========================================================================
__global__ void zero_kernel(float* p, int n)
{
    for (int i = blockIdx.x * blockDim.x + threadIdx.x; i < n;
         i += gridDim.x * blockDim.x)
        p[i] = 0.f;
}

// ==========================================================================
// fused reduction over lower-triangular W:
//   trace(inv) = ||W||_F^2,  proj = sum_r (W_row_r . c)^2
// ==========================================================================
__global__ void reduce_kernel(const float* __restrict__ c)
{
    __shared__ float r2[256], ry[256];
    int r = blockIdx.x;
    const float* row = g_W + (size_t)r * N;
    float s2 = 0.f, sy = 0.f;
    for (int j = threadIdx.x; j <= r; j += 256) {
        float v = row[j];
        s2 += v * v;
        sy += v * c[j];
    }
    r2[threadIdx.x] = s2; ry[threadIdx.x] = sy;
    __syncthreads();
    for (int o = 128; o > 0; o >>= 1) {
        if (threadIdx.x < o) {
            r2[threadIdx.x] += r2[threadIdx.x + o];
            ry[threadIdx.x] += ry[threadIdx.x + o];
        }
        __syncthreads();
    }
    if (threadIdx.x == 0) {
        atomicAdd(&g_scal[0], r2[0]);
        float y = ry[0];
        atomicAdd(&g_scal[1], y * y);
    }
}

__global__ void final_kernel(float* out)
{
    __shared__ float red[256];
    float s = 0.f;
    for (int i = threadIdx.x; i < N; i += 256)
        s += logf(g_S[(size_t)i * N + i]);
    red[threadIdx.x] = s; __syncthreads();
    for (int o = 128; o > 0; o >>= 1) {
        if (threadIdx.x < o) red[threadIdx.x] += red[threadIdx.x + o];
        __syncthreads();
    }
    if (threadIdx.x == 0) {
        float nrd = expf(red[0] * (2.0f / (float)N));
        out[0] = (float)N / 5.0f +
                 nrd * ((0.5f - 1.0f / PI_F) * g_scal[0] + g_scal[1] / PI_F);
    }
}

// ==========================================================================
// host orchestration
// ==========================================================================
extern "C" void kernel_launch(void* const* d_in, const int* in_sizes, int n_in,
                              void* d_out, int out_size)
{
    (void)in_sizes; (void)n_in; (void)out_size;
    const float* x     = (const float*)d_in[0];
    const float* c     = (const float*)d_in[1];
    const float* alpha = (const float*)d_in[2];
    float* out = (float*)d_out;

    float *Sp, *Wp, *iDp, *T2p, *scalp;
    __nv_bfloat16 *hip, *lop, *Phip, *Plop;
    cudaGetSymbolAddress((void**)&Sp,    g_S);
    cudaGetSymbolAddress((void**)&Wp,    g_W);
    cudaGetSymbolAddress((void**)&iDp,   g_invD);
    cudaGetSymbolAddress((void**)&T2p,   g_T2);
    cudaGetSymbolAddress((void**)&scalp, g_scal);
    cudaGetSymbolAddress((void**)&hip,   g_hi);
    cudaGetSymbolAddress((void**)&lop,   g_lo);
    cudaGetSymbolAddress((void**)&Phip,  g_Phi);
    cudaGetSymbolAddress((void**)&Plop,  g_Plo);

    int potrf_smem = 2 * NB * LDA * (int)sizeof(float);
    cudaFuncSetAttribute(potrf_invert,
                         cudaFuncAttributeMaxDynamicSharedMemorySize,
                         potrf_smem);
    cudaFuncSetAttribute(mma_nt_kernel<1, 0>,
                         cudaFuncAttributeMaxDynamicSharedMemorySize,
                         GRAM_SMEM);
    cudaFuncSetAttribute(mma_nt_kernel<3, 1>,
                         cudaFuncAttributeMaxDynamicSharedMemorySize,
                         GRAM_SMEM);
    cudaFuncSetAttribute(gemm_nt_split_mma,
                         cudaFuncAttributeMaxDynamicSharedMemorySize,
                         TS_SMEM);
    cudaFuncSetAttribute(gemm_nn_mma<1, 0>,
                         cudaFuncAttributeMaxDynamicSharedMemorySize,
                         NN_SMEM);
    cudaFuncSetAttribute(gemm_nn_mma<0, 1>,
                         cudaFuncAttributeMaxDynamicSharedMemorySize,
                         NN_SMEM);

    // 1. gram via pure-hi bf16 mma (1 product), fused diag snapshot
    split_kernel<<<4096, 256>>>(x);
    mma_nt_kernel<1, 0><<<NBLK * (NBLK + 1) / 2, 256, GRAM_SMEM>>>(
        hip, lop, hip, lop, D, Sp, N, D, 1.0f / (float)D);

    // 2. arc-cosine kernel step
    step_kernel<<<dim3(N / 32, N / 8), dim3(32, 8)>>>(alpha);

    // 3. blocked Cholesky (in place, lower)
    for (int k = 0; k < NBLK; k++) {
        potrf_invert<<<1, PT, potrf_smem>>>(k);
        if (k < NBLK - 1) {
            int rows = (NBLK - 1 - k) * NB;
            gemm_nt_split_mma<<<rows / 128, 256, TS_SMEM>>>(
                Sp + (size_t)(k + 1) * NB * N + (size_t)k * NB, N,
                iDp + (size_t)k * NB * NB,
                Sp + (size_t)(k + 1) * NB * N + (size_t)k * NB, N,
                Phip, Plop);
            int T2 = NBLK - 1 - k;
            mma_nt_kernel<3, 1><<<T2 * (T2 + 1) / 2, 256, GRAM_SMEM>>>(
                Phip, Plop, Phip, Plop, NB,
                Sp + (size_t)(k + 1) * NB * N + (size_t)(k + 1) * NB, N,
                NB, 1.0f);
        }
    }

    // 4. divide & conquer triangular inversion: W = L^{-1} (mma, masked)
    //    (diag blocks of W already written by potrf_invert)
    for (int lev = 0; lev < 4; lev++) {
        int s = 128 << lev;
        int pairs = N / (2 * s);
        size_t strW = (size_t)2 * s * (N + 1);
        gemm_nn_mma<1, 0><<<dim3(s / 128, s / 128, pairs), 256, NN_SMEM>>>(
            Wp + (size_t)s * N + s, strW, N,
            Sp + (size_t)s * N,     strW, N,
            T2p, (size_t)s * s, s,
            s, 1.0f);
        gemm_nn_mma<0, 1><<<dim3(s / 128, s / 128, pairs), 256, NN_SMEM>>>(
            T2p, (size_t)s * s, s,
            Wp, strW, N,
            Wp + (size_t)s * N, strW, N,
            s, -1.0f);
    }

    // 5. fused reductions + final scalar
    zero_kernel<<<1, 32>>>(scalp, 4);
    reduce_kernel<<<N, 256>>>(c);
    final_kernel<<<1, 256>>>(out);
}

// round 16
// speedup vs baseline: 1.0936x; 1.0936x over previous
#include <cuda_runtime.h>
#include <cuda_bf16.h>
#include <math.h>
#include <stdint.h>

#define N 2048
#define D 16384
#define NB 128
#define LDA 129            // padded smem stride (bank-conflict-free columns)
#define NBLK 16            // N / NB
#define PI_F 3.14159265358979323846f

// ---------------- device scratch (no allocations allowed) ----------------
__device__ float g_S[(size_t)N * N];        // gram / sigma / L (lower, in place)
__device__ float g_W[(size_t)N * N];        // L^{-1} (lower)
__device__ float g_invD[NBLK * NB * NB];    // per-panel inv(L11)
__device__ float g_T2[(size_t)1024 * 1024]; // D&C inversion scratch
__device__ float g_diag[N];                 // diag snapshot
__device__ float g_scal[4];                 // [0]=trace acc, [1]=proj acc
__device__ __nv_bfloat16 g_hi[(size_t)N * D];
__device__ __nv_bfloat16 g_lo[(size_t)N * D];
__device__ __nv_bfloat16 g_Phi[(size_t)N * NB];  // TRSM panel, bf16 hi
__device__ __nv_bfloat16 g_Plo[(size_t)N * NB];  // TRSM panel, bf16 lo

// ==========================================================================
__device__ __forceinline__ uint32_t smem_u32(const void* p) {
    uint32_t a;
    asm("{ .reg .u64 t; cvta.to.shared.u64 t, %1; cvt.u32.u64 %0, t; }"
        : "=r"(a) : "l"(p));
    return a;
}
__device__ __forceinline__ uint32_t bf2pack(float a, float b) {
    __nv_bfloat162 h(__float2bfloat16(a), __float2bfloat16(b));
    return *(uint32_t*)&h;
}

// ==========================================================================
// split conversion: x -> hi (bf16) only (gram is pure hi*hi)
// ==========================================================================
__global__ void split_kernel(const float* __restrict__ x)
{
    size_t total = (size_t)N * D / 4;
    const float4* x4 = (const float4*)x;
    for (size_t i = blockIdx.x * (size_t)blockDim.x + threadIdx.x; i < total;
         i += (size_t)gridDim.x * blockDim.x) {
        float4 v = x4[i];
        __nv_bfloat162* hp = (__nv_bfloat162*)(g_hi + i * 4);
        hp[0] = __nv_bfloat162(__float2bfloat16(v.x), __float2bfloat16(v.y));
        hp[1] = __nv_bfloat162(__float2bfloat16(v.z), __float2bfloat16(v.w));
    }
}

// ==========================================================================
// templated bf16-split NT mma kernel over lower tile pairs:
// NPROD=1: acc = Ahi*Bhi^T (gram)  NPROD=3: + Ahi*Blo^T + Alo*Bhi^T (SYRK)
// MODE=0:  C = clip(acc*scale, -1, 1) + writes g_diag on diag tiles
// MODE=1:  C -= acc
// ==========================================================================
#define BKG 32
#define GTILE_B (128 * 40 * 2)
#define GRAM_SMEM (2 * 4 * GTILE_B)

__device__ __forceinline__ void ldsm_x4(uint32_t* r, uint32_t addr) {
    asm volatile("ldmatrix.sync.aligned.m8n8.x4.shared.b16 {%0,%1,%2,%3}, [%4];"
                 : "=r"(r[0]), "=r"(r[1]), "=r"(r[2]), "=r"(r[3]) : "r"(addr));
}
__device__ __forceinline__ void ldsm_x2(uint32_t* r, uint32_t addr) {
    asm volatile("ldmatrix.sync.aligned.m8n8.x2.shared.b16 {%0,%1}, [%2];"
                 : "=r"(r[0]), "=r"(r[1]) : "r"(addr));
}
__device__ __forceinline__ void ldsm_x2_trans(uint32_t* r, uint32_t addr) {
    asm volatile("ldmatrix.sync.aligned.m8n8.x2.trans.shared.b16 {%0,%1}, [%2];"
                 : "=r"(r[0]), "=r"(r[1]) : "r"(addr));
}
__device__ __forceinline__ void mma_bf16(float* d, const uint32_t* a,
                                         const uint32_t* b) {
    asm volatile(
        "mma.sync.aligned.m16n8k16.row.col.f32.bf16.bf16.f32 "
        "{%0,%1,%2,%3}, {%4,%5,%6,%7}, {%8,%9}, {%0,%1,%2,%3};"
        : "+f"(d[0]), "+f"(d[1]), "+f"(d[2]), "+f"(d[3])
        : "r"(a[0]), "r"(a[1]), "r"(a[2]), "r"(a[3]), "r"(b[0]), "r"(b[1]));
}
#define CP_ASYNC(dst, src) \
    asm volatile("cp.async.cg.shared.global [%0], [%1], 16;" \
                 :: "r"(dst), "l"(src))
#define CP_COMMIT() asm volatile("cp.async.commit_group;" ::: "memory")

template <int NPROD, int MODE>
__global__ __launch_bounds__(256, 1)
void mma_nt_kernel(const __nv_bfloat16* __restrict__ Ahi,
                   const __nv_bfloat16* __restrict__ Alo,
                   const __nv_bfloat16* __restrict__ Bhi,
                   const __nv_bfloat16* __restrict__ Blo,
                   size_t lda, float* __restrict__ Cbase, int ldc,
                   int K, float scale)
{
    extern __shared__ char dsm[];
    uint32_t sbase = smem_u32(dsm);

    int tid  = threadIdx.x;
    int wid  = tid >> 5;
    int lane = tid & 31;

    int t = blockIdx.x;
    int bi = (int)((sqrtf(8.f * (float)t + 1.f) - 1.f) * 0.5f);
    while ((bi + 1) * (bi + 2) / 2 <= t) bi++;
    while (bi * (bi + 1) / 2 > t) bi--;
    int bj = t - bi * (bi + 1) / 2;

    const __nv_bfloat16* srcs[4] = {
        Ahi + (size_t)bi * 128 * lda,
        Alo + (size_t)bi * 128 * lda,
        Bhi + (size_t)bj * 128 * lda,
        Blo + (size_t)bj * 128 * lda
    };

    int m0w = (wid & 1) * 64;
    int n0w = (wid >> 1) * 32;

    float acc[4][4][4];
#pragma unroll
    for (int im = 0; im < 4; im++)
#pragma unroll
        for (int jn = 0; jn < 4; jn++)
#pragma unroll
            for (int e = 0; e < 4; e++) acc[im][jn][e] = 0.f;

    const int S = K / BKG;

    {
#pragma unroll
        for (int it = 0; it < 8; it++) {
            int idx = tid + it * 256;
            int tile = idx >> 9;
            int rem = idx & 511;
            int r = rem >> 2, ch = rem & 3;
            if (NPROD == 1 && (tile & 1)) continue;
            if (NPROD == 2 && tile == 1) continue;
            uint32_t dst = sbase + (uint32_t)tile * GTILE_B + r * 80 + ch * 16;
            CP_ASYNC(dst, srcs[tile] + (size_t)r * lda + ch * 8);
        }
        CP_COMMIT();
    }

#pragma unroll 1
    for (int s = 0; s < S; s++) {
        if (s + 1 < S) {
            int k0 = (s + 1) * BKG;
            uint32_t boff = (uint32_t)((s + 1) & 1) * (4 * GTILE_B);
#pragma unroll
            for (int it = 0; it < 8; it++) {
                int idx = tid + it * 256;
                int tile = idx >> 9;
                int rem = idx & 511;
                int r = rem >> 2, ch = rem & 3;
                if (NPROD == 1 && (tile & 1)) continue;
                if (NPROD == 2 && tile == 1) continue;
                uint32_t dst = sbase + boff + (uint32_t)tile * GTILE_B +
                               r * 80 + ch * 16;
                CP_ASYNC(dst, srcs[tile] + (size_t)r * lda + k0 + ch * 8);
            }
            CP_COMMIT();
            asm volatile("cp.async.wait_group 1;" ::: "memory");
        } else {
            asm volatile("cp.async.wait_group 0;" ::: "memory");
        }
        __syncthreads();

        uint32_t buf = sbase + (uint32_t)(s & 1) * (4 * GTILE_B);
        uint32_t Ahi_b = buf;
        uint32_t Alo_b = buf + GTILE_B;
        uint32_t Bhi_b = buf + 2 * GTILE_B;
        uint32_t Blo_b = buf + 3 * GTILE_B;

#pragma unroll
        for (int ks = 0; ks < 2; ks++) {
            int kof = ks * 16;
            int arow = lane & 15;
            int acol = kof + 8 * (lane >> 4);
            uint32_t ah[4][4], al[4][4];
#pragma unroll
            for (int im = 0; im < 4; im++) {
                uint32_t ro = (uint32_t)(m0w + im * 16 + arow) * 80 + acol * 2;
                ldsm_x4(ah[im], Ahi_b + ro);
                if (NPROD == 3) ldsm_x4(al[im], Alo_b + ro);
            }
            int brow = lane & 7;
            int bcol = kof + 8 * ((lane >> 3) & 1);
            uint32_t bh[4][2], bl[4][2];
#pragma unroll
            for (int jn = 0; jn < 4; jn++) {
                uint32_t ro = (uint32_t)(n0w + jn * 8 + brow) * 80 + bcol * 2;
                ldsm_x2(bh[jn], Bhi_b + ro);
                if (NPROD >= 2) ldsm_x2(bl[jn], Blo_b + ro);
            }
#pragma unroll
            for (int im = 0; im < 4; im++)
#pragma unroll
                for (int jn = 0; jn < 4; jn++) {
                    mma_bf16(acc[im][jn], ah[im], bh[jn]);
                    if (NPROD >= 2) mma_bf16(acc[im][jn], ah[im], bl[jn]);
                    if (NPROD == 3) mma_bf16(acc[im][jn], al[im], bh[jn]);
                }
        }
        __syncthreads();
    }

#pragma unroll
    for (int im = 0; im < 4; im++) {
        int row = bi * 128 + m0w + im * 16 + (lane >> 2);
#pragma unroll
        for (int jn = 0; jn < 4; jn++) {
            int col = bj * 128 + n0w + jn * 8 + (lane & 3) * 2;
            float* p0 = Cbase + (size_t)row * ldc + col;
            float* p1 = Cbase + (size_t)(row + 8) * ldc + col;
            if (MODE == 0) {
                float v0 = fminf(fmaxf(acc[im][jn][0] * scale, -1.f), 1.f);
                float v1 = fminf(fmaxf(acc[im][jn][1] * scale, -1.f), 1.f);
                float v2 = fminf(fmaxf(acc[im][jn][2] * scale, -1.f), 1.f);
                float v3 = fminf(fmaxf(acc[im][jn][3] * scale, -1.f), 1.f);
                p0[0] = v0; p0[1] = v1; p1[0] = v2; p1[1] = v3;
                if (bi == bj) {   // fused diag snapshot
                    if (col == row)         g_diag[row]     = v0;
                    if (col + 1 == row)     g_diag[row]     = v1;
                    if (col == row + 8)     g_diag[row + 8] = v2;
                    if (col + 1 == row + 8) g_diag[row + 8] = v3;
                }
            } else {
                p0[0] -= acc[im][jn][0];
                p0[1] -= acc[im][jn][1];
                p1[0] -= acc[im][jn][2];
                p1[1] -= acc[im][jn][3];
            }
        }
    }
}

// ==========================================================================
// TRSM panel GEMM (FFMA, 64x64 tiles, high occupancy — latency-optimal on
// the serial chain): C = A * B^T; writes fp32 L into S and bf16 hi/lo
// split panels for the mma SYRK.
// ==========================================================================
__global__ __launch_bounds__(256, 2)
void gemm_nt_split(const float* __restrict__ A, int lda,
                   const float* __restrict__ B, int ldb,
                   float* __restrict__ Cs, int ldcs,
                   __nv_bfloat16* __restrict__ Phi,
                   __nv_bfloat16* __restrict__ Plo, int K)
{
    __shared__ float As[16][64];
    __shared__ float Bs[16][64];
    int bi = blockIdx.y, bj = blockIdx.x;
    int tid = threadIdx.x;
    int tx = tid & 15, ty = tid >> 4;

    const float* Ab = A + (size_t)(bi * 64) * lda;
    const float* Bb = B + (size_t)(bj * 64) * ldb;

    int arow = tid >> 2, akk = (tid & 3) << 2;

    float acc[4][4];
#pragma unroll
    for (int i = 0; i < 4; i++)
#pragma unroll
        for (int j = 0; j < 4; j++) acc[i][j] = 0.f;

    for (int k0 = 0; k0 < K; k0 += 16) {
        float4 va = *(const float4*)(Ab + (size_t)arow * lda + k0 + akk);
        float4 vb = *(const float4*)(Bb + (size_t)arow * ldb + k0 + akk);
        As[akk + 0][arow] = va.x; As[akk + 1][arow] = va.y;
        As[akk + 2][arow] = va.z; As[akk + 3][arow] = va.w;
        Bs[akk + 0][arow] = vb.x; Bs[akk + 1][arow] = vb.y;
        Bs[akk + 2][arow] = vb.z; Bs[akk + 3][arow] = vb.w;
        __syncthreads();
#pragma unroll
        for (int kk = 0; kk < 16; kk++) {
            float4 a = *(const float4*)&As[kk][ty * 4];
            float4 b = *(const float4*)&Bs[kk][tx * 4];
            float av[4] = {a.x, a.y, a.z, a.w};
            float bv[4] = {b.x, b.y, b.z, b.w};
#pragma unroll
            for (int i = 0; i < 4; i++)
#pragma unroll
                for (int j = 0; j < 4; j++)
                    acc[i][j] += av[i] * bv[j];
        }
        __syncthreads();
    }

#pragma unroll
    for (int i = 0; i < 4; i++) {
        int row = bi * 64 + ty * 4 + i;
#pragma unroll
        for (int j = 0; j < 4; j++) {
            int col = bj * 64 + tx * 4 + j;
            float v = acc[i][j];
            Cs[(size_t)row * ldcs + col] = v;
            __nv_bfloat16 h = __float2bfloat16(v);
            Phi[(size_t)row * NB + col] = h;
            Plo[(size_t)row * NB + col] =
                __float2bfloat16(v - __bfloat162float(h));
        }
    }
}

// ==========================================================================
// batched NN mma GEMM with on-the-fly fp32 -> bf16 hi/lo split (3 products)
// MASKA/MASKB: diag-aligned lower-triangular operand masking.
// ==========================================================================
#define NNT_A 10240                  // 128 rows * 80 B
#define NNT_B 8704                   // 32 rows * 272 B
#define NN_STAGE (2 * NNT_A + 2 * NNT_B)
#define NN_SMEM (2 * NN_STAGE)       // 75776 B

template <int MASKA, int MASKB>
__global__ __launch_bounds__(256, 1)
void gemm_nn_mma(const float* __restrict__ A, size_t strA, int lda,
                 const float* __restrict__ B, size_t strB, int ldb,
                 float* __restrict__ C, size_t strC, int ldc,
                 int K, float alpha)
{
    A += (size_t)blockIdx.z * strA;
    B += (size_t)blockIdx.z * strB;
    C += (size_t)blockIdx.z * strC;

    extern __shared__ char dsm[];
    uint32_t sbase = smem_u32(dsm);

    int tid = threadIdx.x, wid = tid >> 5, lane = tid & 31;
    int bi = blockIdx.y, bj = blockIdx.x;
    int m0w = (wid & 1) * 64;
    int n0w = (wid >> 1) * 32;

    float acc[4][4][4];
#pragma unroll
    for (int im = 0; im < 4; im++)
#pragma unroll
        for (int jn = 0; jn < 4; jn++)
#pragma unroll
            for (int e = 0; e < 4; e++) acc[im][jn][e] = 0.f;

    const int S = K / 32;

    float4 ra[4], rb[4];

    auto ldreg = [&](int s) {
#pragma unroll
        for (int it = 0; it < 4; it++) {
            int idx = tid + it * 256;
            int r = idx >> 3, f = idx & 7;
            float4 v = *(const float4*)(A + (size_t)(bi * 128 + r) * lda +
                                        s * 32 + f * 4);
            if (MASKA) {
                int row = bi * 128 + r;
                int cb = s * 32 + f * 4;
                if (cb + 0 > row) v.x = 0.f;
                if (cb + 1 > row) v.y = 0.f;
                if (cb + 2 > row) v.z = 0.f;
                if (cb + 3 > row) v.w = 0.f;
            }
            ra[it] = v;
        }
#pragma unroll
        for (int it = 0; it < 4; it++) {
            int idx = tid + it * 256;
            int kk = idx >> 5, f = idx & 31;
            float4 v = *(const float4*)(B + (size_t)(s * 32 + kk) * ldb +
                                        bj * 128 + f * 4);
            if (MASKB) {
                int krow = s * 32 + kk;
                int cb = bj * 128 + f * 4;
                if (cb + 0 > krow) v.x = 0.f;
                if (cb + 1 > krow) v.y = 0.f;
                if (cb + 2 > krow) v.z = 0.f;
                if (cb + 3 > krow) v.w = 0.f;
            }
            rb[it] = v;
        }
    };

    auto streg = [&](int b) {
        char* sm = dsm + (size_t)b * NN_STAGE;
#pragma unroll
        for (int it = 0; it < 4; it++) {
            int idx = tid + it * 256;
            int r = idx >> 3, f = idx & 7;
            float4 v = ra[it];
            float hx = __bfloat162float(__float2bfloat16(v.x));
            float hy = __bfloat162float(__float2bfloat16(v.y));
            float hz = __bfloat162float(__float2bfloat16(v.z));
            float hw = __bfloat162float(__float2bfloat16(v.w));
            uint2 hi = { bf2pack(v.x, v.y), bf2pack(v.z, v.w) };
            uint2 lo = { bf2pack(v.x - hx, v.y - hy),
                         bf2pack(v.z - hz, v.w - hw) };
            *(uint2*)(sm + r * 80 + f * 8)         = hi;
            *(uint2*)(sm + NNT_A + r * 80 + f * 8) = lo;
        }
#pragma unroll
        for (int it = 0; it < 4; it++) {
            int idx = tid + it * 256;
            int kk = idx >> 5, f = idx & 31;
            float4 v = rb[it];
            float hx = __bfloat162float(__float2bfloat16(v.x));
            float hy = __bfloat162float(__float2bfloat16(v.y));
            float hz = __bfloat162float(__float2bfloat16(v.z));
            float hw = __bfloat162float(__float2bfloat16(v.w));
            uint2 hi = { bf2pack(v.x, v.y), bf2pack(v.z, v.w) };
            uint2 lo = { bf2pack(v.x - hx, v.y - hy),
                         bf2pack(v.z - hz, v.w - hw) };
            *(uint2*)(sm + 2 * NNT_A + kk * 272 + f * 8)         = hi;
            *(uint2*)(sm + 2 * NNT_A + NNT_B + kk * 272 + f * 8) = lo;
        }
    };

    ldreg(0);
    streg(0);
    __syncthreads();

#pragma unroll 1
    for (int s = 0; s < S; s++) {
        if (s + 1 < S) ldreg(s + 1);

        uint32_t buf = sbase + (uint32_t)(s & 1) * NN_STAGE;
        uint32_t Ahi_b = buf;
        uint32_t Alo_b = buf + NNT_A;
        uint32_t Bhi_b = buf + 2 * NNT_A;
        uint32_t Blo_b = buf + 2 * NNT_A + NNT_B;

#pragma unroll
        for (int ks = 0; ks < 2; ks++) {
            int kof = ks * 16;
            int arow = lane & 15;
            int acol = kof + 8 * (lane >> 4);
            uint32_t ah[4][4], al[4][4];
#pragma unroll
            for (int im = 0; im < 4; im++) {
                uint32_t ro = (uint32_t)(m0w + im * 16 + arow) * 80 + acol * 2;
                ldsm_x4(ah[im], Ahi_b + ro);
                ldsm_x4(al[im], Alo_b + ro);
            }
            int l16 = lane & 15;
            int brow = kof + (l16 & 7) + 8 * (l16 >> 3);
            uint32_t bh[4][2], bl[4][2];
#pragma unroll
            for (int jn = 0; jn < 4; jn++) {
                int n0 = n0w + jn * 8;
                uint32_t ro = (uint32_t)brow * 272 + n0 * 2;
                ldsm_x2_trans(bh[jn], Bhi_b + ro);
                ldsm_x2_trans(bl[jn], Blo_b + ro);
            }
#pragma unroll
            for (int im = 0; im < 4; im++)
#pragma unroll
                for (int jn = 0; jn < 4; jn++) {
                    mma_bf16(acc[im][jn], ah[im], bh[jn]);
                    mma_bf16(acc[im][jn], ah[im], bl[jn]);
                    mma_bf16(acc[im][jn], al[im], bh[jn]);
                }
        }

        if (s + 1 < S) streg((s + 1) & 1);
        __syncthreads();
    }

#pragma unroll
    for (int im = 0; im < 4; im++) {
        int row = bi * 128 + m0w + im * 16 + (lane >> 2);
#pragma unroll
        for (int jn = 0; jn < 4; jn++) {
            int col = bj * 128 + n0w + jn * 8 + (lane & 3) * 2;
            C[(size_t)row * ldc + col]           = alpha * acc[im][jn][0];
            C[(size_t)row * ldc + col + 1]       = alpha * acc[im][jn][1];
            C[(size_t)(row + 8) * ldc + col]     = alpha * acc[im][jn][2];
            C[(size_t)(row + 8) * ldc + col + 1] = alpha * acc[im][jn][3];
        }
    }
}

// ==========================================================================
__global__ void step_kernel(const float* __restrict__ alpha_p)
{
    int j = blockIdx.x * 32 + threadIdx.x;
    int i = blockIdx.y * 8 + threadIdx.y;
    if (i >= N || j > i) return;
    float a  = *alpha_p;
    float a2 = a * a;
    float cross = sqrtf(g_diag[i] * g_diag[j]);
    float s = g_S[(size_t)i * N + j];
    float m = fminf(fmaxf(s / cross, -1.f), 1.f);
    float q = 1.f - m * m;
    float sq, ac;
    if (q > 0.f) { sq = sqrtf(q); ac = acosf(m); }
    else         { sq = 0.f;      ac = (m > 0.f) ? 0.f : PI_F; }
    float f  = (sq + m * (PI_F - ac)) / PI_F;
    float ts = cross * f;
    float ov = (s + a2 * ts) / (1.f + a2);
    g_S[(size_t)i * N + j] = fminf(fmaxf(ov, -1.f), 1.f);
}

// ==========================================================================
// panel factorization + inversion of 128x128 diag block (512 threads).
// Epilogue writes L to S, inv(L11) to g_invD AND to W's diag block.
// ==========================================================================
#define PT 512
__global__ __launch_bounds__(PT, 1)
void potrf_invert(int kb)
{
    extern __shared__ float sh[];
    float* A = sh;                 // NB x NB stride LDA (L, lower)
    float* W = sh + NB * LDA;      // NB x NB stride LDA (inv(L), lower)
    __shared__ float Ts[3 * 1056];
    int tid = threadIdx.x;
    int base = kb * NB;

    for (int idx = tid; idx < NB * 32; idx += PT) {
        int i = idx >> 5, j4 = (idx & 31) << 2;
        float4 v = *(const float4*)&g_S[(size_t)(base + i) * N + base + j4];
        A[i * LDA + j4 + 0] = v.x;
        A[i * LDA + j4 + 1] = v.y;
        A[i * LDA + j4 + 2] = v.z;
        A[i * LDA + j4 + 3] = v.w;
    }
    __syncthreads();

    for (int p = 0; p < 4; p++) {
        int off = p * 32;

        if (tid < 32) {
            const unsigned FULL = 0xffffffffu;
            int r = tid;
            float ar[32];
#pragma unroll
            for (int t = 0; t < 32; t++)
                ar[t] = (t <= r) ? A[(off + r) * LDA + off + t] : 0.f;
            float rs_reg = 0.f;
#pragma unroll
            for (int j = 0; j < 32; j++) {
                float d   = __shfl_sync(FULL, ar[j], j);
                float rsj = rsqrtf(d);
                float lj  = ar[j] * rsj;
                ar[j] = lj;
                if (r == j) rs_reg = rsj;
#pragma unroll
                for (int t = j + 1; t < 32; t++) {
                    float ltj = __shfl_sync(FULL, lj, t);
                    ar[t] -= lj * ltj;
                }
            }
            int c = r;
            float w[32];
#pragma unroll
            for (int t = 0; t < 32; t++) w[t] = 0.f;
#pragma unroll
            for (int i = 0; i < 32; i++) {
                float s = (i == c) ? 1.f : 0.f;
#pragma unroll
                for (int t = 0; t < i; t++) {
                    float lit = __shfl_sync(FULL, ar[t], i);
                    s -= lit * w[t];
                }
                float rsi = __shfl_sync(FULL, rs_reg, i);
                w[i] = (i >= c) ? s * rsi : 0.f;
            }
#pragma unroll
            for (int t = 0; t < 32; t++)
                if (t <= r) A[(off + r) * LDA + off + t] = ar[t];
#pragma unroll
            for (int i = 0; i < 32; i++)
                W[(off + i) * LDA + off + c] = w[i];
        }
        __syncthreads();

        int nr = NB - off - 32;
        if (nr > 0) {
            int ntr = (nr >> 2) * 8;
            float acc[4][4];
            int tr = 0, tc = 0;
            if (tid < ntr) {
                tr = (tid >> 3) * 4;
                tc = (tid & 7) * 4;
#pragma unroll
                for (int r = 0; r < 4; r++)
#pragma unroll
                    for (int cidx = 0; cidx < 4; cidx++) acc[r][cidx] = 0.f;
#pragma unroll 8
                for (int k = 0; k < 32; k++) {
                    float av[4], wv[4];
#pragma unroll
                    for (int r = 0; r < 4; r++)
                        av[r] = A[(off + 32 + tr + r) * LDA + off + k];
#pragma unroll
                    for (int cidx = 0; cidx < 4; cidx++)
                        wv[cidx] = W[(off + tc + cidx) * LDA + off + k];
#pragma unroll
                    for (int r = 0; r < 4; r++)
#pragma unroll
                        for (int cidx = 0; cidx < 4; cidx++)
                            acc[r][cidx] += av[r] * wv[cidx];
                }
            }
            __syncthreads();
            if (tid < ntr) {
#pragma unroll
                for (int r = 0; r < 4; r++)
#pragma unroll
                    for (int cidx = 0; cidx < 4; cidx++)
                        A[(off + 32 + tr + r) * LDA + off + tc + cidx] =
                            acc[r][cidx];
            }
            __syncthreads();

            int nt = nr >> 2;
            int ntot = nt * (nt + 1) / 2;
            for (int tId = tid; tId < ntot; tId += PT) {
                int ti = (int)((sqrtf(8.f * (float)tId + 1.f) - 1.f) * 0.5f);
                while ((ti + 1) * (ti + 2) / 2 <= tId) ti++;
                while (ti * (ti + 1) / 2 > tId) ti--;
                int tj = tId - ti * (ti + 1) / 2;
                int i0 = off + 32 + ti * 4;
                int t0 = off + 32 + tj * 4;
                float a2[4][4];
#pragma unroll
                for (int r = 0; r < 4; r++)
#pragma unroll
                    for (int cidx = 0; cidx < 4; cidx++) a2[r][cidx] = 0.f;
#pragma unroll 8
                for (int k = 0; k < 32; k++) {
                    float av[4], bv[4];
#pragma unroll
                    for (int r = 0; r < 4; r++)
                        av[r] = A[(i0 + r) * LDA + off + k];
#pragma unroll
                    for (int cidx = 0; cidx < 4; cidx++)
                        bv[cidx] = A[(t0 + cidx) * LDA + off + k];
#pragma unroll
                    for (int r = 0; r < 4; r++)
#pragma unroll
                        for (int cidx = 0; cidx < 4; cidx++)
                            a2[r][cidx] += av[r] * bv[cidx];
                }
#pragma unroll
                for (int r = 0; r < 4; r++)
#pragma unroll
                    for (int cidx = 0; cidx < 4; cidx++) {
                        int ii = i0 + r, tt = t0 + cidx;
                        if (tt <= ii) A[ii * LDA + tt] -= a2[r][cidx];
                    }
            }
            __syncthreads();
        }
    }

    for (int ib = 1; ib < 4; ib++) {
        for (int tId = tid; tId < ib * 64; tId += PT) {
            int j = tId >> 6;
            int e = tId & 63;
            int r0 = (e >> 3) * 4, c0 = (e & 7) * 4;
            float acc[4][4];
#pragma unroll
            for (int r = 0; r < 4; r++)
#pragma unroll
                for (int cidx = 0; cidx < 4; cidx++) acc[r][cidx] = 0.f;
            for (int tb = j; tb < ib; tb++) {
#pragma unroll 8
                for (int k = 0; k < 32; k++) {
                    float lv[4], wv[4];
#pragma unroll
                    for (int r = 0; r < 4; r++)
                        lv[r] = A[(32 * ib + r0 + r) * LDA + 32 * tb + k];
#pragma unroll
                    for (int cidx = 0; cidx < 4; cidx++)
                        wv[cidx] = W[(32 * tb + k) * LDA + 32 * j + c0 + cidx];
#pragma unroll
                    for (int r = 0; r < 4; r++)
#pragma unroll
                        for (int cidx = 0; cidx < 4; cidx++)
                            acc[r][cidx] += lv[r] * wv[cidx];
                }
            }
#pragma unroll
            for (int r = 0; r < 4; r++)
#pragma unroll
                for (int cidx = 0; cidx < 4; cidx++)
                    Ts[j * 1056 + (r0 + r) * 33 + c0 + cidx] = acc[r][cidx];
        }
        __syncthreads();
        for (int tId = tid; tId < ib * 64; tId += PT) {
            int j = tId >> 6;
            int e = tId & 63;
            int r0 = (e >> 3) * 4, c0 = (e & 7) * 4;
            float acc[4][4];
#pragma unroll
            for (int r = 0; r < 4; r++)
#pragma unroll
                for (int cidx = 0; cidx < 4; cidx++) acc[r][cidx] = 0.f;
#pragma unroll 8
            for (int k = 0; k < 32; k++) {
                float wv[4], tv[4];
#pragma unroll
                for (int r = 0; r < 4; r++)
                    wv[r] = W[(32 * ib + r0 + r) * LDA + 32 * ib + k];
#pragma unroll
                for (int cidx = 0; cidx < 4; cidx++)
                    tv[cidx] = Ts[j * 1056 + k * 33 + c0 + cidx];
#pragma unroll
                for (int r = 0; r < 4; r++)
#pragma unroll
                    for (int cidx = 0; cidx < 4; cidx++)
                        acc[r][cidx] += wv[r] * tv[cidx];
            }
#pragma unroll
            for (int r = 0; r < 4; r++)
#pragma unroll
                for (int cidx = 0; cidx < 4; cidx++)
                    W[(32 * ib + r0 + r) * LDA + 32 * j + c0 + cidx] =
                        -acc[r][cidx];
        }
        __syncthreads();
    }

    for (int idx = tid; idx < NB * NB; idx += PT) {
        int i = idx >> 7, j = idx & 127;
        if (j <= i) g_S[(size_t)(base + i) * N + base + j] = A[i * LDA + j];
        float wv = ((j >> 5) <= (i >> 5)) ? W[i * LDA + j] : 0.f;
        g_invD[(size_t)kb * NB * NB + idx] = wv;
        g_W[(size_t)(base + i) * N + base + j] = wv;   // fused copy_diag
    }
}

// ==========================================================================
__global__ void zero_kernel(float* p, int n)
{
    for (int i = blockIdx.x * blockDim.x + threadIdx.x; i < n;
         i += gridDim.x * blockDim.x)
        p[i] = 0.f;
}

// ==========================================================================
// fused reduction over lower-triangular W:
//   trace(inv) = ||W||_F^2,  proj = sum_r (W_row_r . c)^2
// ==========================================================================
__global__ void reduce_kernel(const float* __restrict__ c)
{
    __shared__ float r2[256], ry[256];
    int r = blockIdx.x;
    const float* row = g_W + (size_t)r * N;
    float s2 = 0.f, sy = 0.f;
    for (int j = threadIdx.x; j <= r; j += 256) {
        float v = row[j];
        s2 += v * v;
        sy += v * c[j];
    }
    r2[threadIdx.x] = s2; ry[threadIdx.x] = sy;
    __syncthreads();
    for (int o = 128; o > 0; o >>= 1) {
        if (threadIdx.x < o) {
            r2[threadIdx.x] += r2[threadIdx.x + o];
            ry[threadIdx.x] += ry[threadIdx.x + o];
        }
        __syncthreads();
    }
    if (threadIdx.x == 0) {
        atomicAdd(&g_scal[0], r2[0]);
        float y = ry[0];
        atomicAdd(&g_scal[1], y * y);
    }
}

__global__ void final_kernel(float* out)
{
    __shared__ float red[256];
    float s = 0.f;
    for (int i = threadIdx.x; i < N; i += 256)
        s += logf(g_S[(size_t)i * N + i]);
    red[threadIdx.x] = s; __syncthreads();
    for (int o = 128; o > 0; o >>= 1) {
        if (threadIdx.x < o) red[threadIdx.x] += red[threadIdx.x + o];
        __syncthreads();
    }
    if (threadIdx.x == 0) {
        float nrd = expf(red[0] * (2.0f / (float)N));
        out[0] = (float)N / 5.0f +
                 nrd * ((0.5f - 1.0f / PI_F) * g_scal[0] + g_scal[1] / PI_F);
    }
}

// ==========================================================================
// host orchestration
// ==========================================================================
extern "C" void kernel_launch(void* const* d_in, const int* in_sizes, int n_in,
                              void* d_out, int out_size)
{
    (void)in_sizes; (void)n_in; (void)out_size;
    const float* x     = (const float*)d_in[0];
    const float* c     = (const float*)d_in[1];
    const float* alpha = (const float*)d_in[2];
    float* out = (float*)d_out;

    float *Sp, *Wp, *iDp, *T2p, *scalp;
    __nv_bfloat16 *hip, *lop, *Phip, *Plop;
    cudaGetSymbolAddress((void**)&Sp,    g_S);
    cudaGetSymbolAddress((void**)&Wp,    g_W);
    cudaGetSymbolAddress((void**)&iDp,   g_invD);
    cudaGetSymbolAddress((void**)&T2p,   g_T2);
    cudaGetSymbolAddress((void**)&scalp, g_scal);
    cudaGetSymbolAddress((void**)&hip,   g_hi);
    cudaGetSymbolAddress((void**)&lop,   g_lo);
    cudaGetSymbolAddress((void**)&Phip,  g_Phi);
    cudaGetSymbolAddress((void**)&Plop,  g_Plo);

    int potrf_smem = 2 * NB * LDA * (int)sizeof(float);
    cudaFuncSetAttribute(potrf_invert,
                         cudaFuncAttributeMaxDynamicSharedMemorySize,
                         potrf_smem);
    cudaFuncSetAttribute(mma_nt_kernel<1, 0>,
                         cudaFuncAttributeMaxDynamicSharedMemorySize,
                         GRAM_SMEM);
    cudaFuncSetAttribute(mma_nt_kernel<3, 1>,
                         cudaFuncAttributeMaxDynamicSharedMemorySize,
                         GRAM_SMEM);
    cudaFuncSetAttribute(gemm_nn_mma<1, 0>,
                         cudaFuncAttributeMaxDynamicSharedMemorySize,
                         NN_SMEM);
    cudaFuncSetAttribute(gemm_nn_mma<0, 1>,
                         cudaFuncAttributeMaxDynamicSharedMemorySize,
                         NN_SMEM);

    // 1. gram via pure-hi bf16 mma (1 product), fused diag snapshot
    split_kernel<<<4096, 256>>>(x);
    mma_nt_kernel<1, 0><<<NBLK * (NBLK + 1) / 2, 256, GRAM_SMEM>>>(
        hip, lop, hip, lop, D, Sp, N, D, 1.0f / (float)D);

    // 2. arc-cosine kernel step
    step_kernel<<<dim3(N / 32, N / 8), dim3(32, 8)>>>(alpha);

    // 3. blocked Cholesky (in place, lower)
    for (int k = 0; k < NBLK; k++) {
        potrf_invert<<<1, PT, potrf_smem>>>(k);
        if (k < NBLK - 1) {
            int rows = (NBLK - 1 - k) * NB;
            gemm_nt_split<<<dim3(2, rows / 64), 256>>>(
                Sp + (size_t)(k + 1) * NB * N + (size_t)k * NB, N,
                iDp + (size_t)k * NB * NB, NB,
                Sp + (size_t)(k + 1) * NB * N + (size_t)k * NB, N,
                Phip, Plop, NB);
            int T2 = NBLK - 1 - k;
            mma_nt_kernel<3, 1><<<T2 * (T2 + 1) / 2, 256, GRAM_SMEM>>>(
                Phip, Plop, Phip, Plop, NB,
                Sp + (size_t)(k + 1) * NB * N + (size_t)(k + 1) * NB, N,
                NB, 1.0f);
        }
    }

    // 4. divide & conquer triangular inversion: W = L^{-1} (mma, masked)
    //    (diag blocks of W already written by potrf_invert)
    for (int lev = 0; lev < 4; lev++) {
        int s = 128 << lev;
        int pairs = N / (2 * s);
        size_t strW = (size_t)2 * s * (N + 1);
        gemm_nn_mma<1, 0><<<dim3(s / 128, s / 128, pairs), 256, NN_SMEM>>>(
            Wp + (size_t)s * N + s, strW, N,
            Sp + (size_t)s * N,     strW, N,
            T2p, (size_t)s * s, s,
            s, 1.0f);
        gemm_nn_mma<0, 1><<<dim3(s / 128, s / 128, pairs), 256, NN_SMEM>>>(
            T2p, (size_t)s * s, s,
            Wp, strW, N,
            Wp + (size_t)s * N, strW, N,
            s, -1.0f);
    }

    // 5. fused reductions + final scalar
    zero_kernel<<<1, 32>>>(scalp, 4);
    reduce_kernel<<<N, 256>>>(c);
    final_kernel<<<1, 256>>>(out);
}

// round 17
// speedup vs baseline: 1.1093x; 1.0143x over previous
#include <cuda_runtime.h>
#include <cuda_bf16.h>
#include <math.h>
#include <stdint.h>

#define N 2048
#define D 16384
#define NB 128
#define LDA 129            // padded smem stride (bank-conflict-free columns)
#define NBLK 16            // N / NB
#define PI_F 3.14159265358979323846f

// ---------------- device scratch (no allocations allowed) ----------------
__device__ float g_S[(size_t)N * N];        // gram / sigma / L (lower, in place)
__device__ float g_W[(size_t)N * N];        // L^{-1} (lower)
__device__ float g_invD[NBLK * NB * NB];    // per-panel inv(L11)
__device__ float g_T2[(size_t)1024 * 1024]; // D&C inversion scratch
__device__ float g_diag[N];                 // diag snapshot
__device__ float g_scal[4];                 // [0]=trace acc, [1]=proj acc
__device__ __nv_bfloat16 g_hi[(size_t)N * D];
__device__ __nv_bfloat16 g_lo[(size_t)N * D];
__device__ __nv_bfloat16 g_Phi[(size_t)N * NB];  // TRSM panel, bf16 hi
__device__ __nv_bfloat16 g_Plo[(size_t)N * NB];  // TRSM panel, bf16 lo

// ==========================================================================
__device__ __forceinline__ uint32_t smem_u32(const void* p) {
    uint32_t a;
    asm("{ .reg .u64 t; cvta.to.shared.u64 t, %1; cvt.u32.u64 %0, t; }"
        : "=r"(a) : "l"(p));
    return a;
}
__device__ __forceinline__ uint32_t bf2pack(float a, float b) {
    __nv_bfloat162 h(__float2bfloat16(a), __float2bfloat16(b));
    return *(uint32_t*)&h;
}

// ==========================================================================
// split conversion: x -> hi (bf16); also zeroes the scalar accumulators
// ==========================================================================
__global__ void split_kernel(const float* __restrict__ x)
{
    if (blockIdx.x == 0 && threadIdx.x < 4) g_scal[threadIdx.x] = 0.f;
    size_t total = (size_t)N * D / 4;
    const float4* x4 = (const float4*)x;
    for (size_t i = blockIdx.x * (size_t)blockDim.x + threadIdx.x; i < total;
         i += (size_t)gridDim.x * blockDim.x) {
        float4 v = x4[i];
        __nv_bfloat162* hp = (__nv_bfloat162*)(g_hi + i * 4);
        hp[0] = __nv_bfloat162(__float2bfloat16(v.x), __float2bfloat16(v.y));
        hp[1] = __nv_bfloat162(__float2bfloat16(v.z), __float2bfloat16(v.w));
    }
}

// ==========================================================================
// templated bf16-split NT mma kernel over lower tile pairs:
// NPROD=1: acc = Ahi*Bhi^T (gram)  NPROD=3: + Ahi*Blo^T + Alo*Bhi^T (SYRK)
// MODE=0:  C = clip(acc*scale, -1, 1) + writes g_diag on diag tiles
// MODE=1:  C -= acc
// ==========================================================================
#define BKG 32
#define GTILE_B (128 * 40 * 2)
#define GRAM_SMEM (2 * 4 * GTILE_B)

__device__ __forceinline__ void ldsm_x4(uint32_t* r, uint32_t addr) {
    asm volatile("ldmatrix.sync.aligned.m8n8.x4.shared.b16 {%0,%1,%2,%3}, [%4];"
                 : "=r"(r[0]), "=r"(r[1]), "=r"(r[2]), "=r"(r[3]) : "r"(addr));
}
__device__ __forceinline__ void ldsm_x2(uint32_t* r, uint32_t addr) {
    asm volatile("ldmatrix.sync.aligned.m8n8.x2.shared.b16 {%0,%1}, [%2];"
                 : "=r"(r[0]), "=r"(r[1]) : "r"(addr));
}
__device__ __forceinline__ void ldsm_x2_trans(uint32_t* r, uint32_t addr) {
    asm volatile("ldmatrix.sync.aligned.m8n8.x2.trans.shared.b16 {%0,%1}, [%2];"
                 : "=r"(r[0]), "=r"(r[1]) : "r"(addr));
}
__device__ __forceinline__ void mma_bf16(float* d, const uint32_t* a,
                                         const uint32_t* b) {
    asm volatile(
        "mma.sync.aligned.m16n8k16.row.col.f32.bf16.bf16.f32 "
        "{%0,%1,%2,%3}, {%4,%5,%6,%7}, {%8,%9}, {%0,%1,%2,%3};"
        : "+f"(d[0]), "+f"(d[1]), "+f"(d[2]), "+f"(d[3])
        : "r"(a[0]), "r"(a[1]), "r"(a[2]), "r"(a[3]), "r"(b[0]), "r"(b[1]));
}
#define CP_ASYNC(dst, src) \
    asm volatile("cp.async.cg.shared.global [%0], [%1], 16;" \
                 :: "r"(dst), "l"(src))
#define CP_COMMIT() asm volatile("cp.async.commit_group;" ::: "memory")

template <int NPROD, int MODE>
__global__ __launch_bounds__(256, 1)
void mma_nt_kernel(const __nv_bfloat16* __restrict__ Ahi,
                   const __nv_bfloat16* __restrict__ Alo,
                   const __nv_bfloat16* __restrict__ Bhi,
                   const __nv_bfloat16* __restrict__ Blo,
                   size_t lda, float* __restrict__ Cbase, int ldc,
                   int K, float scale)
{
    extern __shared__ char dsm[];
    uint32_t sbase = smem_u32(dsm);

    int tid  = threadIdx.x;
    int wid  = tid >> 5;
    int lane = tid & 31;

    int t = blockIdx.x;
    int bi = (int)((sqrtf(8.f * (float)t + 1.f) - 1.f) * 0.5f);
    while ((bi + 1) * (bi + 2) / 2 <= t) bi++;
    while (bi * (bi + 1) / 2 > t) bi--;
    int bj = t - bi * (bi + 1) / 2;

    const __nv_bfloat16* srcs[4] = {
        Ahi + (size_t)bi * 128 * lda,
        Alo + (size_t)bi * 128 * lda,
        Bhi + (size_t)bj * 128 * lda,
        Blo + (size_t)bj * 128 * lda
    };

    int m0w = (wid & 1) * 64;
    int n0w = (wid >> 1) * 32;

    float acc[4][4][4];
#pragma unroll
    for (int im = 0; im < 4; im++)
#pragma unroll
        for (int jn = 0; jn < 4; jn++)
#pragma unroll
            for (int e = 0; e < 4; e++) acc[im][jn][e] = 0.f;

    const int S = K / BKG;

    {
#pragma unroll
        for (int it = 0; it < 8; it++) {
            int idx = tid + it * 256;
            int tile = idx >> 9;
            int rem = idx & 511;
            int r = rem >> 2, ch = rem & 3;
            if (NPROD == 1 && (tile & 1)) continue;
            if (NPROD == 2 && tile == 1) continue;
            uint32_t dst = sbase + (uint32_t)tile * GTILE_B + r * 80 + ch * 16;
            CP_ASYNC(dst, srcs[tile] + (size_t)r * lda + ch * 8);
        }
        CP_COMMIT();
    }

#pragma unroll 1
    for (int s = 0; s < S; s++) {
        if (s + 1 < S) {
            int k0 = (s + 1) * BKG;
            uint32_t boff = (uint32_t)((s + 1) & 1) * (4 * GTILE_B);
#pragma unroll
            for (int it = 0; it < 8; it++) {
                int idx = tid + it * 256;
                int tile = idx >> 9;
                int rem = idx & 511;
                int r = rem >> 2, ch = rem & 3;
                if (NPROD == 1 && (tile & 1)) continue;
                if (NPROD == 2 && tile == 1) continue;
                uint32_t dst = sbase + boff + (uint32_t)tile * GTILE_B +
                               r * 80 + ch * 16;
                CP_ASYNC(dst, srcs[tile] + (size_t)r * lda + k0 + ch * 8);
            }
            CP_COMMIT();
            asm volatile("cp.async.wait_group 1;" ::: "memory");
        } else {
            asm volatile("cp.async.wait_group 0;" ::: "memory");
        }
        __syncthreads();

        uint32_t buf = sbase + (uint32_t)(s & 1) * (4 * GTILE_B);
        uint32_t Ahi_b = buf;
        uint32_t Alo_b = buf + GTILE_B;
        uint32_t Bhi_b = buf + 2 * GTILE_B;
        uint32_t Blo_b = buf + 3 * GTILE_B;

#pragma unroll
        for (int ks = 0; ks < 2; ks++) {
            int kof = ks * 16;
            int arow = lane & 15;
            int acol = kof + 8 * (lane >> 4);
            uint32_t ah[4][4], al[4][4];
#pragma unroll
            for (int im = 0; im < 4; im++) {
                uint32_t ro = (uint32_t)(m0w + im * 16 + arow) * 80 + acol * 2;
                ldsm_x4(ah[im], Ahi_b + ro);
                if (NPROD == 3) ldsm_x4(al[im], Alo_b + ro);
            }
            int brow = lane & 7;
            int bcol = kof + 8 * ((lane >> 3) & 1);
            uint32_t bh[4][2], bl[4][2];
#pragma unroll
            for (int jn = 0; jn < 4; jn++) {
                uint32_t ro = (uint32_t)(n0w + jn * 8 + brow) * 80 + bcol * 2;
                ldsm_x2(bh[jn], Bhi_b + ro);
                if (NPROD >= 2) ldsm_x2(bl[jn], Blo_b + ro);
            }
#pragma unroll
            for (int im = 0; im < 4; im++)
#pragma unroll
                for (int jn = 0; jn < 4; jn++) {
                    mma_bf16(acc[im][jn], ah[im], bh[jn]);
                    if (NPROD >= 2) mma_bf16(acc[im][jn], ah[im], bl[jn]);
                    if (NPROD == 3) mma_bf16(acc[im][jn], al[im], bh[jn]);
                }
        }
        __syncthreads();
    }

#pragma unroll
    for (int im = 0; im < 4; im++) {
        int row = bi * 128 + m0w + im * 16 + (lane >> 2);
#pragma unroll
        for (int jn = 0; jn < 4; jn++) {
            int col = bj * 128 + n0w + jn * 8 + (lane & 3) * 2;
            float* p0 = Cbase + (size_t)row * ldc + col;
            float* p1 = Cbase + (size_t)(row + 8) * ldc + col;
            if (MODE == 0) {
                float v0 = fminf(fmaxf(acc[im][jn][0] * scale, -1.f), 1.f);
                float v1 = fminf(fmaxf(acc[im][jn][1] * scale, -1.f), 1.f);
                float v2 = fminf(fmaxf(acc[im][jn][2] * scale, -1.f), 1.f);
                float v3 = fminf(fmaxf(acc[im][jn][3] * scale, -1.f), 1.f);
                p0[0] = v0; p0[1] = v1; p1[0] = v2; p1[1] = v3;
                if (bi == bj) {   // fused diag snapshot
                    if (col == row)         g_diag[row]     = v0;
                    if (col + 1 == row)     g_diag[row]     = v1;
                    if (col == row + 8)     g_diag[row + 8] = v2;
                    if (col + 1 == row + 8) g_diag[row + 8] = v3;
                }
            } else {
                p0[0] -= acc[im][jn][0];
                p0[1] -= acc[im][jn][1];
                p1[0] -= acc[im][jn][2];
                p1[1] -= acc[im][jn][3];
            }
        }
    }
}

// ==========================================================================
// TRSM panel GEMM (FFMA, 64x64 tiles, register-prefetch double buffer):
// C = A * B^T; writes fp32 L into S and bf16 hi/lo split panels.
// ==========================================================================
__global__ __launch_bounds__(256, 2)
void gemm_nt_split(const float* __restrict__ A, int lda,
                   const float* __restrict__ B, int ldb,
                   float* __restrict__ Cs, int ldcs,
                   __nv_bfloat16* __restrict__ Phi,
                   __nv_bfloat16* __restrict__ Plo, int K)
{
    __shared__ float As[16][64];
    __shared__ float Bs[16][64];
    int bi = blockIdx.y, bj = blockIdx.x;
    int tid = threadIdx.x;
    int tx = tid & 15, ty = tid >> 4;

    const float* Ab = A + (size_t)(bi * 64) * lda;
    const float* Bb = B + (size_t)(bj * 64) * ldb;

    int arow = tid >> 2, akk = (tid & 3) << 2;

    float4 pa = *(const float4*)(Ab + (size_t)arow * lda + akk);
    float4 pb = *(const float4*)(Bb + (size_t)arow * ldb + akk);

    float acc[4][4];
#pragma unroll
    for (int i = 0; i < 4; i++)
#pragma unroll
        for (int j = 0; j < 4; j++) acc[i][j] = 0.f;

    for (int k0 = 0; k0 < K; k0 += 16) {
        if (k0) __syncthreads();
        As[akk + 0][arow] = pa.x; As[akk + 1][arow] = pa.y;
        As[akk + 2][arow] = pa.z; As[akk + 3][arow] = pa.w;
        Bs[akk + 0][arow] = pb.x; Bs[akk + 1][arow] = pb.y;
        Bs[akk + 2][arow] = pb.z; Bs[akk + 3][arow] = pb.w;
        __syncthreads();
        if (k0 + 16 < K) {
            pa = *(const float4*)(Ab + (size_t)arow * lda + k0 + 16 + akk);
            pb = *(const float4*)(Bb + (size_t)arow * ldb + k0 + 16 + akk);
        }
#pragma unroll
        for (int kk = 0; kk < 16; kk++) {
            float4 a = *(const float4*)&As[kk][ty * 4];
            float4 b = *(const float4*)&Bs[kk][tx * 4];
            float av[4] = {a.x, a.y, a.z, a.w};
            float bv[4] = {b.x, b.y, b.z, b.w};
#pragma unroll
            for (int i = 0; i < 4; i++)
#pragma unroll
                for (int j = 0; j < 4; j++)
                    acc[i][j] += av[i] * bv[j];
        }
    }

#pragma unroll
    for (int i = 0; i < 4; i++) {
        int row = bi * 64 + ty * 4 + i;
#pragma unroll
        for (int j = 0; j < 4; j++) {
            int col = bj * 64 + tx * 4 + j;
            float v = acc[i][j];
            Cs[(size_t)row * ldcs + col] = v;
            __nv_bfloat16 h = __float2bfloat16(v);
            Phi[(size_t)row * NB + col] = h;
            Plo[(size_t)row * NB + col] =
                __float2bfloat16(v - __bfloat162float(h));
        }
    }
}

// ==========================================================================
// batched NN mma GEMM with on-the-fly fp32 -> bf16 hi/lo split (3 products)
// MASKA/MASKB: diag-aligned lower-triangular operand masking.
// ==========================================================================
#define NNT_A 10240                  // 128 rows * 80 B
#define NNT_B 8704                   // 32 rows * 272 B
#define NN_STAGE (2 * NNT_A + 2 * NNT_B)
#define NN_SMEM (2 * NN_STAGE)       // 75776 B

template <int MASKA, int MASKB>
__global__ __launch_bounds__(256, 1)
void gemm_nn_mma(const float* __restrict__ A, size_t strA, int lda,
                 const float* __restrict__ B, size_t strB, int ldb,
                 float* __restrict__ C, size_t strC, int ldc,
                 int K, float alpha)
{
    A += (size_t)blockIdx.z * strA;
    B += (size_t)blockIdx.z * strB;
    C += (size_t)blockIdx.z * strC;

    extern __shared__ char dsm[];
    uint32_t sbase = smem_u32(dsm);

    int tid = threadIdx.x, wid = tid >> 5, lane = tid & 31;
    int bi = blockIdx.y, bj = blockIdx.x;
    int m0w = (wid & 1) * 64;
    int n0w = (wid >> 1) * 32;

    float acc[4][4][4];
#pragma unroll
    for (int im = 0; im < 4; im++)
#pragma unroll
        for (int jn = 0; jn < 4; jn++)
#pragma unroll
            for (int e = 0; e < 4; e++) acc[im][jn][e] = 0.f;

    const int S = K / 32;

    float4 ra[4], rb[4];

    auto ldreg = [&](int s) {
#pragma unroll
        for (int it = 0; it < 4; it++) {
            int idx = tid + it * 256;
            int r = idx >> 3, f = idx & 7;
            float4 v = *(const float4*)(A + (size_t)(bi * 128 + r) * lda +
                                        s * 32 + f * 4);
            if (MASKA) {
                int row = bi * 128 + r;
                int cb = s * 32 + f * 4;
                if (cb + 0 > row) v.x = 0.f;
                if (cb + 1 > row) v.y = 0.f;
                if (cb + 2 > row) v.z = 0.f;
                if (cb + 3 > row) v.w = 0.f;
            }
            ra[it] = v;
        }
#pragma unroll
        for (int it = 0; it < 4; it++) {
            int idx = tid + it * 256;
            int kk = idx >> 5, f = idx & 31;
            float4 v = *(const float4*)(B + (size_t)(s * 32 + kk) * ldb +
                                        bj * 128 + f * 4);
            if (MASKB) {
                int krow = s * 32 + kk;
                int cb = bj * 128 + f * 4;
                if (cb + 0 > krow) v.x = 0.f;
                if (cb + 1 > krow) v.y = 0.f;
                if (cb + 2 > krow) v.z = 0.f;
                if (cb + 3 > krow) v.w = 0.f;
            }
            rb[it] = v;
        }
    };

    auto streg = [&](int b) {
        char* sm = dsm + (size_t)b * NN_STAGE;
#pragma unroll
        for (int it = 0; it < 4; it++) {
            int idx = tid + it * 256;
            int r = idx >> 3, f = idx & 7;
            float4 v = ra[it];
            float hx = __bfloat162float(__float2bfloat16(v.x));
            float hy = __bfloat162float(__float2bfloat16(v.y));
            float hz = __bfloat162float(__float2bfloat16(v.z));
            float hw = __bfloat162float(__float2bfloat16(v.w));
            uint2 hi = { bf2pack(v.x, v.y), bf2pack(v.z, v.w) };
            uint2 lo = { bf2pack(v.x - hx, v.y - hy),
                         bf2pack(v.z - hz, v.w - hw) };
            *(uint2*)(sm + r * 80 + f * 8)         = hi;
            *(uint2*)(sm + NNT_A + r * 80 + f * 8) = lo;
        }
#pragma unroll
        for (int it = 0; it < 4; it++) {
            int idx = tid + it * 256;
            int kk = idx >> 5, f = idx & 31;
            float4 v = rb[it];
            float hx = __bfloat162float(__float2bfloat16(v.x));
            float hy = __bfloat162float(__float2bfloat16(v.y));
            float hz = __bfloat162float(__float2bfloat16(v.z));
            float hw = __bfloat162float(__float2bfloat16(v.w));
            uint2 hi = { bf2pack(v.x, v.y), bf2pack(v.z, v.w) };
            uint2 lo = { bf2pack(v.x - hx, v.y - hy),
                         bf2pack(v.z - hz, v.w - hw) };
            *(uint2*)(sm + 2 * NNT_A + kk * 272 + f * 8)         = hi;
            *(uint2*)(sm + 2 * NNT_A + NNT_B + kk * 272 + f * 8) = lo;
        }
    };

    ldreg(0);
    streg(0);
    __syncthreads();

#pragma unroll 1
    for (int s = 0; s < S; s++) {
        if (s + 1 < S) ldreg(s + 1);

        uint32_t buf = sbase + (uint32_t)(s & 1) * NN_STAGE;
        uint32_t Ahi_b = buf;
        uint32_t Alo_b = buf + NNT_A;
        uint32_t Bhi_b = buf + 2 * NNT_A;
        uint32_t Blo_b = buf + 2 * NNT_A + NNT_B;

#pragma unroll
        for (int ks = 0; ks < 2; ks++) {
            int kof = ks * 16;
            int arow = lane & 15;
            int acol = kof + 8 * (lane >> 4);
            uint32_t ah[4][4], al[4][4];
#pragma unroll
            for (int im = 0; im < 4; im++) {
                uint32_t ro = (uint32_t)(m0w + im * 16 + arow) * 80 + acol * 2;
                ldsm_x4(ah[im], Ahi_b + ro);
                ldsm_x4(al[im], Alo_b + ro);
            }
            int l16 = lane & 15;
            int brow = kof + (l16 & 7) + 8 * (l16 >> 3);
            uint32_t bh[4][2], bl[4][2];
#pragma unroll
            for (int jn = 0; jn < 4; jn++) {
                int n0 = n0w + jn * 8;
                uint32_t ro = (uint32_t)brow * 272 + n0 * 2;
                ldsm_x2_trans(bh[jn], Bhi_b + ro);
                ldsm_x2_trans(bl[jn], Blo_b + ro);
            }
#pragma unroll
            for (int im = 0; im < 4; im++)
#pragma unroll
                for (int jn = 0; jn < 4; jn++) {
                    mma_bf16(acc[im][jn], ah[im], bh[jn]);
                    mma_bf16(acc[im][jn], ah[im], bl[jn]);
                    mma_bf16(acc[im][jn], al[im], bh[jn]);
                }
        }

        if (s + 1 < S) streg((s + 1) & 1);
        __syncthreads();
    }

#pragma unroll
    for (int im = 0; im < 4; im++) {
        int row = bi * 128 + m0w + im * 16 + (lane >> 2);
#pragma unroll
        for (int jn = 0; jn < 4; jn++) {
            int col = bj * 128 + n0w + jn * 8 + (lane & 3) * 2;
            C[(size_t)row * ldc + col]           = alpha * acc[im][jn][0];
            C[(size_t)row * ldc + col + 1]       = alpha * acc[im][jn][1];
            C[(size_t)(row + 8) * ldc + col]     = alpha * acc[im][jn][2];
            C[(size_t)(row + 8) * ldc + col + 1] = alpha * acc[im][jn][3];
        }
    }
}

// ==========================================================================
__global__ void step_kernel(const float* __restrict__ alpha_p)
{
    int j = blockIdx.x * 32 + threadIdx.x;
    int i = blockIdx.y * 8 + threadIdx.y;
    if (i >= N || j > i) return;
    float a  = *alpha_p;
    float a2 = a * a;
    float cross = sqrtf(g_diag[i] * g_diag[j]);
    float s = g_S[(size_t)i * N + j];
    float m = fminf(fmaxf(s / cross, -1.f), 1.f);
    float q = 1.f - m * m;
    float sq, ac;
    if (q > 0.f) { sq = sqrtf(q); ac = acosf(m); }
    else         { sq = 0.f;      ac = (m > 0.f) ? 0.f : PI_F; }
    float f  = (sq + m * (PI_F - ac)) / PI_F;
    float ts = cross * f;
    float ov = (s + a2 * ts) / (1.f + a2);
    g_S[(size_t)i * N + j] = fminf(fmaxf(ov, -1.f), 1.f);
}

// ==========================================================================
// panel factorization + inversion of 128x128 diag block (512 threads).
// inv32 uses 4-way partial sums to break the serial FMA chain.
// Epilogue writes L to S, inv(L11) to g_invD AND to W's diag block.
// ==========================================================================
#define PT 512
__global__ __launch_bounds__(PT, 1)
void potrf_invert(int kb)
{
    extern __shared__ float sh[];
    float* A = sh;                 // NB x NB stride LDA (L, lower)
    float* W = sh + NB * LDA;      // NB x NB stride LDA (inv(L), lower)
    __shared__ float Ts[3 * 1056];
    int tid = threadIdx.x;
    int base = kb * NB;

    for (int idx = tid; idx < NB * 32; idx += PT) {
        int i = idx >> 5, j4 = (idx & 31) << 2;
        float4 v = *(const float4*)&g_S[(size_t)(base + i) * N + base + j4];
        A[i * LDA + j4 + 0] = v.x;
        A[i * LDA + j4 + 1] = v.y;
        A[i * LDA + j4 + 2] = v.z;
        A[i * LDA + j4 + 3] = v.w;
    }
    __syncthreads();

    for (int p = 0; p < 4; p++) {
        int off = p * 32;

        if (tid < 32) {
            const unsigned FULL = 0xffffffffu;
            int r = tid;
            float ar[32];
#pragma unroll
            for (int t = 0; t < 32; t++)
                ar[t] = (t <= r) ? A[(off + r) * LDA + off + t] : 0.f;
            float rs_reg = 0.f;
#pragma unroll
            for (int j = 0; j < 32; j++) {
                float d   = __shfl_sync(FULL, ar[j], j);
                float rsj = rsqrtf(d);
                float lj  = ar[j] * rsj;
                ar[j] = lj;
                if (r == j) rs_reg = rsj;
#pragma unroll
                for (int t = j + 1; t < 32; t++) {
                    float ltj = __shfl_sync(FULL, lj, t);
                    ar[t] -= lj * ltj;
                }
            }
            // inv32: lane c = column c; 4-way partial sums break the chain
            int c = r;
            float w[32];
#pragma unroll
            for (int t = 0; t < 32; t++) w[t] = 0.f;
#pragma unroll
            for (int i = 0; i < 32; i++) {
                float s0 = (i == c) ? 1.f : 0.f;
                float s1 = 0.f, s2 = 0.f, s3 = 0.f;
#pragma unroll
                for (int t = 0; t < i; t++) {
                    float lit = __shfl_sync(FULL, ar[t], i);
                    float term = lit * w[t];
                    if ((t & 3) == 0)      s0 -= term;
                    else if ((t & 3) == 1) s1 -= term;
                    else if ((t & 3) == 2) s2 -= term;
                    else                   s3 -= term;
                }
                float rsi = __shfl_sync(FULL, rs_reg, i);
                float s = (s0 + s1) + (s2 + s3);
                w[i] = (i >= c) ? s * rsi : 0.f;
            }
#pragma unroll
            for (int t = 0; t < 32; t++)
                if (t <= r) A[(off + r) * LDA + off + t] = ar[t];
#pragma unroll
            for (int i = 0; i < 32; i++)
                W[(off + i) * LDA + off + c] = w[i];
        }
        __syncthreads();

        int nr = NB - off - 32;
        if (nr > 0) {
            int ntr = (nr >> 2) * 8;
            float acc[4][4];
            int tr = 0, tc = 0;
            if (tid < ntr) {
                tr = (tid >> 3) * 4;
                tc = (tid & 7) * 4;
#pragma unroll
                for (int r = 0; r < 4; r++)
#pragma unroll
                    for (int cidx = 0; cidx < 4; cidx++) acc[r][cidx] = 0.f;
#pragma unroll 8
                for (int k = 0; k < 32; k++) {
                    float av[4], wv[4];
#pragma unroll
                    for (int r = 0; r < 4; r++)
                        av[r] = A[(off + 32 + tr + r) * LDA + off + k];
#pragma unroll
                    for (int cidx = 0; cidx < 4; cidx++)
                        wv[cidx] = W[(off + tc + cidx) * LDA + off + k];
#pragma unroll
                    for (int r = 0; r < 4; r++)
#pragma unroll
                        for (int cidx = 0; cidx < 4; cidx++)
                            acc[r][cidx] += av[r] * wv[cidx];
                }
            }
            __syncthreads();
            if (tid < ntr) {
#pragma unroll
                for (int r = 0; r < 4; r++)
#pragma unroll
                    for (int cidx = 0; cidx < 4; cidx++)
                        A[(off + 32 + tr + r) * LDA + off + tc + cidx] =
                            acc[r][cidx];
            }
            __syncthreads();

            int nt = nr >> 2;
            int ntot = nt * (nt + 1) / 2;
            for (int tId = tid; tId < ntot; tId += PT) {
                int ti = (int)((sqrtf(8.f * (float)tId + 1.f) - 1.f) * 0.5f);
                while ((ti + 1) * (ti + 2) / 2 <= tId) ti++;
                while (ti * (ti + 1) / 2 > tId) ti--;
                int tj = tId - ti * (ti + 1) / 2;
                int i0 = off + 32 + ti * 4;
                int t0 = off + 32 + tj * 4;
                float a2[4][4];
#pragma unroll
                for (int r = 0; r < 4; r++)
#pragma unroll
                    for (int cidx = 0; cidx < 4; cidx++) a2[r][cidx] = 0.f;
#pragma unroll 8
                for (int k = 0; k < 32; k++) {
                    float av[4], bv[4];
#pragma unroll
                    for (int r = 0; r < 4; r++)
                        av[r] = A[(i0 + r) * LDA + off + k];
#pragma unroll
                    for (int cidx = 0; cidx < 4; cidx++)
                        bv[cidx] = A[(t0 + cidx) * LDA + off + k];
#pragma unroll
                    for (int r = 0; r < 4; r++)
#pragma unroll
                        for (int cidx = 0; cidx < 4; cidx++)
                            a2[r][cidx] += av[r] * bv[cidx];
                }
#pragma unroll
                for (int r = 0; r < 4; r++)
#pragma unroll
                    for (int cidx = 0; cidx < 4; cidx++) {
                        int ii = i0 + r, tt = t0 + cidx;
                        if (tt <= ii) A[ii * LDA + tt] -= a2[r][cidx];
                    }
            }
            __syncthreads();
        }
    }

    for (int ib = 1; ib < 4; ib++) {
        for (int tId = tid; tId < ib * 64; tId += PT) {
            int j = tId >> 6;
            int e = tId & 63;
            int r0 = (e >> 3) * 4, c0 = (e & 7) * 4;
            float acc[4][4];
#pragma unroll
            for (int r = 0; r < 4; r++)
#pragma unroll
                for (int cidx = 0; cidx < 4; cidx++) acc[r][cidx] = 0.f;
            for (int tb = j; tb < ib; tb++) {
#pragma unroll 8
                for (int k = 0; k < 32; k++) {
                    float lv[4], wv[4];
#pragma unroll
                    for (int r = 0; r < 4; r++)
                        lv[r] = A[(32 * ib + r0 + r) * LDA + 32 * tb + k];
#pragma unroll
                    for (int cidx = 0; cidx < 4; cidx++)
                        wv[cidx] = W[(32 * tb + k) * LDA + 32 * j + c0 + cidx];
#pragma unroll
                    for (int r = 0; r < 4; r++)
#pragma unroll
                        for (int cidx = 0; cidx < 4; cidx++)
                            acc[r][cidx] += lv[r] * wv[cidx];
                }
            }
#pragma unroll
            for (int r = 0; r < 4; r++)
#pragma unroll
                for (int cidx = 0; cidx < 4; cidx++)
                    Ts[j * 1056 + (r0 + r) * 33 + c0 + cidx] = acc[r][cidx];
        }
        __syncthreads();
        for (int tId = tid; tId < ib * 64; tId += PT) {
            int j = tId >> 6;
            int e = tId & 63;
            int r0 = (e >> 3) * 4, c0 = (e & 7) * 4;
            float acc[4][4];
#pragma unroll
            for (int r = 0; r < 4; r++)
#pragma unroll
                for (int cidx = 0; cidx < 4; cidx++) acc[r][cidx] = 0.f;
#pragma unroll 8
            for (int k = 0; k < 32; k++) {
                float wv[4], tv[4];
#pragma unroll
                for (int r = 0; r < 4; r++)
                    wv[r] = W[(32 * ib + r0 + r) * LDA + 32 * ib + k];
#pragma unroll
                for (int cidx = 0; cidx < 4; cidx++)
                    tv[cidx] = Ts[j * 1056 + k * 33 + c0 + cidx];
#pragma unroll
                for (int r = 0; r < 4; r++)
#pragma unroll
                    for (int cidx = 0; cidx < 4; cidx++)
                        acc[r][cidx] += wv[r] * tv[cidx];
            }
#pragma unroll
            for (int r = 0; r < 4; r++)
#pragma unroll
                for (int cidx = 0; cidx < 4; cidx++)
                    W[(32 * ib + r0 + r) * LDA + 32 * j + c0 + cidx] =
                        -acc[r][cidx];
        }
        __syncthreads();
    }

    for (int idx = tid; idx < NB * NB; idx += PT) {
        int i = idx >> 7, j = idx & 127;
        if (j <= i) g_S[(size_t)(base + i) * N + base + j] = A[i * LDA + j];
        float wv = ((j >> 5) <= (i >> 5)) ? W[i * LDA + j] : 0.f;
        g_invD[(size_t)kb * NB * NB + idx] = wv;
        g_W[(size_t)(base + i) * N + base + j] = wv;   // fused copy_diag
    }
}

// ==========================================================================
// fused reduction over lower-triangular W:
//   trace(inv) = ||W||_F^2,  proj = sum_r (W_row_r . c)^2
// ==========================================================================
__global__ void reduce_kernel(const float* __restrict__ c)
{
    __shared__ float r2[256], ry[256];
    int r = blockIdx.x;
    const float* row = g_W + (size_t)r * N;
    float s2 = 0.f, sy = 0.f;
    for (int j = threadIdx.x; j <= r; j += 256) {
        float v = row[j];
        s2 += v * v;
        sy += v * c[j];
    }
    r2[threadIdx.x] = s2; ry[threadIdx.x] = sy;
    __syncthreads();
    for (int o = 128; o > 0; o >>= 1) {
        if (threadIdx.x < o) {
            r2[threadIdx.x] += r2[threadIdx.x + o];
            ry[threadIdx.x] += ry[threadIdx.x + o];
        }
        __syncthreads();
    }
    if (threadIdx.x == 0) {
        atomicAdd(&g_scal[0], r2[0]);
        float y = ry[0];
        atomicAdd(&g_scal[1], y * y);
    }
}

__global__ void final_kernel(float* out)
{
    __shared__ float red[256];
    float s = 0.f;
    for (int i = threadIdx.x; i < N; i += 256)
        s += logf(g_S[(size_t)i * N + i]);
    red[threadIdx.x] = s; __syncthreads();
    for (int o = 128; o > 0; o >>= 1) {
        if (threadIdx.x < o) red[threadIdx.x] += red[threadIdx.x + o];
        __syncthreads();
    }
    if (threadIdx.x == 0) {
        float nrd = expf(red[0] * (2.0f / (float)N));
        out[0] = (float)N / 5.0f +
                 nrd * ((0.5f - 1.0f / PI_F) * g_scal[0] + g_scal[1] / PI_F);
    }
}

// ==========================================================================
// host orchestration
// ==========================================================================
extern "C" void kernel_launch(void* const* d_in, const int* in_sizes, int n_in,
                              void* d_out, int out_size)
{
    (void)in_sizes; (void)n_in; (void)out_size;
    const float* x     = (const float*)d_in[0];
    const float* c     = (const float*)d_in[1];
    const float* alpha = (const float*)d_in[2];
    float* out = (float*)d_out;

    float *Sp, *Wp, *iDp, *T2p;
    __nv_bfloat16 *hip, *lop, *Phip, *Plop;
    cudaGetSymbolAddress((void**)&Sp,    g_S);
    cudaGetSymbolAddress((void**)&Wp,    g_W);
    cudaGetSymbolAddress((void**)&iDp,   g_invD);
    cudaGetSymbolAddress((void**)&T2p,   g_T2);
    cudaGetSymbolAddress((void**)&hip,   g_hi);
    cudaGetSymbolAddress((void**)&lop,   g_lo);
    cudaGetSymbolAddress((void**)&Phip,  g_Phi);
    cudaGetSymbolAddress((void**)&Plop,  g_Plo);

    int potrf_smem = 2 * NB * LDA * (int)sizeof(float);
    cudaFuncSetAttribute(potrf_invert,
                         cudaFuncAttributeMaxDynamicSharedMemorySize,
                         potrf_smem);
    cudaFuncSetAttribute(mma_nt_kernel<1, 0>,
                         cudaFuncAttributeMaxDynamicSharedMemorySize,
                         GRAM_SMEM);
    cudaFuncSetAttribute(mma_nt_kernel<3, 1>,
                         cudaFuncAttributeMaxDynamicSharedMemorySize,
                         GRAM_SMEM);
    cudaFuncSetAttribute(gemm_nn_mma<1, 0>,
                         cudaFuncAttributeMaxDynamicSharedMemorySize,
                         NN_SMEM);
    cudaFuncSetAttribute(gemm_nn_mma<0, 1>,
                         cudaFuncAttributeMaxDynamicSharedMemorySize,
                         NN_SMEM);

    // 1. gram via pure-hi bf16 mma (1 product), fused diag snapshot + zero
    split_kernel<<<4096, 256>>>(x);
    mma_nt_kernel<1, 0><<<NBLK * (NBLK + 1) / 2, 256, GRAM_SMEM>>>(
        hip, lop, hip, lop, D, Sp, N, D, 1.0f / (float)D);

    // 2. arc-cosine kernel step
    step_kernel<<<dim3(N / 32, N / 8), dim3(32, 8)>>>(alpha);

    // 3. blocked Cholesky (in place, lower)
    for (int k = 0; k < NBLK; k++) {
        potrf_invert<<<1, PT, potrf_smem>>>(k);
        if (k < NBLK - 1) {
            int rows = (NBLK - 1 - k) * NB;
            gemm_nt_split<<<dim3(2, rows / 64), 256>>>(
                Sp + (size_t)(k + 1) * NB * N + (size_t)k * NB, N,
                iDp + (size_t)k * NB * NB, NB,
                Sp + (size_t)(k + 1) * NB * N + (size_t)k * NB, N,
                Phip, Plop, NB);
            int T2 = NBLK - 1 - k;
            mma_nt_kernel<3, 1><<<T2 * (T2 + 1) / 2, 256, GRAM_SMEM>>>(
                Phip, Plop, Phip, Plop, NB,
                Sp + (size_t)(k + 1) * NB * N + (size_t)(k + 1) * NB, N,
                NB, 1.0f);
        }
    }

    // 4. divide & conquer triangular inversion: W = L^{-1} (mma, masked)
    for (int lev = 0; lev < 4; lev++) {
        int s = 128 << lev;
        int pairs = N / (2 * s);
        size_t strW = (size_t)2 * s * (N + 1);
        gemm_nn_mma<1, 0><<<dim3(s / 128, s / 128, pairs), 256, NN_SMEM>>>(
            Wp + (size_t)s * N + s, strW, N,
            Sp + (size_t)s * N,     strW, N,
            T2p, (size_t)s * s, s,
            s, 1.0f);
        gemm_nn_mma<0, 1><<<dim3(s / 128, s / 128, pairs), 256, NN_SMEM>>>(
            T2p, (size_t)s * s, s,
            Wp, strW, N,
            Wp + (size_t)s * N, strW, N,
            s, -1.0f);
    }

    // 5. fused reductions + final scalar
    reduce_kernel<<<N, 256>>>(c);
    final_kernel<<<1, 256>>>(out);
}